// round 3
// baseline (speedup 1.0000x reference)
#include <cuda_runtime.h>
#include <cstdint>

#define NNODES 100000
#define EMAX   1700000
#define HID    64
#define FIN    128
#define NCLS   40

// ------------------------------ device scratch ------------------------------
__device__ float g_bufA[NNODES * HID];
__device__ float g_bufB[NNODES * HID];
__device__ float g_as[NNODES];
__device__ float g_ad[NNODES];
__device__ int   g_deg[NNODES];
__device__ int   g_off[NNODES + 1];
__device__ int   g_pos[NNODES];      // temp: inclusive scan, then scatter cursor
__device__ int   g_csr_src[EMAX];
__device__ int   g_esrc[EMAX];
__device__ int   g_edst[EMAX];
__device__ int   g_bsum[128];
__device__ int   g_boff[128];
__device__ int   g_idx32;            // 1 if edge_index is int32, 0 if int64

__device__ __forceinline__ float lrelu(float x) { return x > 0.f ? x : 0.2f * x; }

// ------------------------------ dtype detect + convert ----------------------
// If data is int64 node indices (< 2^31, non-negative), every odd 32-bit word
// is zero. Any nonzero odd word => int32 layout.
__global__ void k_detect(const int* __restrict__ w, int nwords) {
    __shared__ int nz;
    if (threadIdx.x == 0) nz = 0;
    __syncthreads();
    int n = nwords < 4096 ? nwords : 4096;
    int found = 0;
    for (int i = 2 * threadIdx.x + 1; i < n; i += 2 * blockDim.x)
        if (w[i] != 0) found = 1;
    if (found) atomicExch(&nz, 1);
    __syncthreads();
    if (threadIdx.x == 0) g_idx32 = nz;
}

__global__ void k_convert(const void* __restrict__ ei, int E) {
    int e = blockIdx.x * blockDim.x + threadIdx.x;
    if (e >= 2 * E) return;
    int is32 = g_idx32;
    int v = is32 ? ((const int*)ei)[e] : (int)((const long long*)ei)[e];
    if (e < E) g_esrc[e] = v;
    else       g_edst[e - E] = v;
}

// ------------------------------ CSR build -----------------------------------
__global__ void k_zero_deg() {
    int i = blockIdx.x * blockDim.x + threadIdx.x;
    if (i < NNODES) g_deg[i] = 0;
}

__global__ void k_hist(int E) {
    int e = blockIdx.x * blockDim.x + threadIdx.x;
    if (e < E) atomicAdd(&g_deg[g_edst[e]], 1);
}

__global__ void k_scan1() {
    __shared__ int sh[1024];
    int i = blockIdx.x * 1024 + threadIdx.x;
    int v = (i < NNODES) ? g_deg[i] : 0;
    sh[threadIdx.x] = v;
    __syncthreads();
    for (int o = 1; o < 1024; o <<= 1) {
        int t = 0;
        if (threadIdx.x >= o) t = sh[threadIdx.x - o];
        __syncthreads();
        sh[threadIdx.x] += t;
        __syncthreads();
    }
    if (i < NNODES) g_pos[i] = sh[threadIdx.x];   // inclusive within block
    if (threadIdx.x == 1023) g_bsum[blockIdx.x] = sh[1023];
}

__global__ void k_scan2(int nb) {
    if (threadIdx.x == 0 && blockIdx.x == 0) {
        int run = 0;
        for (int b = 0; b < nb; b++) { g_boff[b] = run; run += g_bsum[b]; }
    }
}

__global__ void k_scan3() {
    int i = blockIdx.x * 1024 + threadIdx.x;
    if (i < NNODES) {
        int incl = g_pos[i] + g_boff[blockIdx.x];
        int excl = incl - g_deg[i];
        g_off[i] = excl;
        g_pos[i] = excl;
        if (i == NNODES - 1) g_off[NNODES] = incl;
    }
}

__global__ void k_scatter(int E) {
    int e = blockIdx.x * blockDim.x + threadIdx.x;
    if (e < E) {
        int d = g_edst[e];
        int p = atomicAdd(&g_pos[d], 1);
        g_csr_src[p] = g_esrc[e];
    }
}

// ------------------------------ tiled GEMM ----------------------------------
// out[nrows, NC] = act(X[nrows, K] @ W[K, NC] (+ bias)); optional attention dot
// fusion: g_as[row] = out_row . attS, g_ad[row] = out_row . attD (raw, pre-act).
// Block = 256 threads: cg = t&15 -> 4 consecutive cols, rg = t>>4 -> 2 rows.
// Tile = 32 rows.
template <int K, int NC, bool ATT, bool BIAS, bool RELU>
__global__ void k_gemm(const float* __restrict__ X, const float* __restrict__ Wg,
                       const float* __restrict__ bias,
                       const float* __restrict__ attS, const float* __restrict__ attD,
                       float* __restrict__ out) {
    extern __shared__ float smem[];
    float* sW  = smem;                  // [K][64] (padded row width 64)
    float* sX  = smem + K * 64;         // [32][K]
    float* sAS = sX + 32 * K;           // [64] (only if ATT)
    float* sAD = sAS + 64;

    for (int i = threadIdx.x; i < K * 64; i += 256) sW[i] = 0.f;
    __syncthreads();
    for (int i = threadIdx.x; i < K * NC; i += 256)
        sW[(i / NC) * 64 + (i % NC)] = Wg[i];
    if (ATT) {
        for (int i = threadIdx.x; i < NC; i += 256) { sAS[i] = attS[i]; sAD[i] = attD[i]; }
    }
    __syncthreads();

    const int cg = threadIdx.x & 15;
    const int rg = threadIdx.x >> 4;
    const int r0 = rg * 2, r1 = r0 + 1;
    const int ntiles = NNODES / 32;

    for (int tile = blockIdx.x; tile < ntiles; tile += gridDim.x) {
        const float* xrow = X + (size_t)tile * 32 * K;
        for (int i = threadIdx.x * 4; i < 32 * K; i += 1024)
            *(float4*)(sX + i) = *(const float4*)(xrow + i);
        __syncthreads();

        float a0x = 0, a0y = 0, a0z = 0, a0w = 0;
        float a1x = 0, a1y = 0, a1z = 0, a1w = 0;
#pragma unroll 8
        for (int k = 0; k < K; k++) {
            float x0 = sX[r0 * K + k];
            float x1 = sX[r1 * K + k];
            float4 w = *(const float4*)&sW[k * 64 + cg * 4];
            a0x = fmaf(x0, w.x, a0x); a0y = fmaf(x0, w.y, a0y);
            a0z = fmaf(x0, w.z, a0z); a0w = fmaf(x0, w.w, a0w);
            a1x = fmaf(x1, w.x, a1x); a1y = fmaf(x1, w.y, a1y);
            a1z = fmaf(x1, w.z, a1z); a1w = fmaf(x1, w.w, a1w);
        }

        int c = cg * 4;
        if (c < NC) {
            float4 o0 = {a0x, a0y, a0z, a0w};
            float4 o1 = {a1x, a1y, a1z, a1w};
            if (BIAS) {
                float4 b = *(const float4*)&bias[c];
                o0.x += b.x; o0.y += b.y; o0.z += b.z; o0.w += b.w;
                o1.x += b.x; o1.y += b.y; o1.z += b.z; o1.w += b.w;
            }
            if (RELU) {
                o0.x = fmaxf(o0.x, 0.f); o0.y = fmaxf(o0.y, 0.f);
                o0.z = fmaxf(o0.z, 0.f); o0.w = fmaxf(o0.w, 0.f);
                o1.x = fmaxf(o1.x, 0.f); o1.y = fmaxf(o1.y, 0.f);
                o1.z = fmaxf(o1.z, 0.f); o1.w = fmaxf(o1.w, 0.f);
            }
            *(float4*)&out[(size_t)(tile * 32 + r0) * NC + c] = o0;
            *(float4*)&out[(size_t)(tile * 32 + r1) * NC + c] = o1;
        }
        if (ATT) {
            float4 s4 = *(const float4*)&sAS[c];
            float4 d4 = *(const float4*)&sAD[c];
            float ps0 = a0x * s4.x + a0y * s4.y + a0z * s4.z + a0w * s4.w;
            float pd0 = a0x * d4.x + a0y * d4.y + a0z * d4.z + a0w * d4.w;
            float ps1 = a1x * s4.x + a1y * s4.y + a1z * s4.z + a1w * s4.w;
            float pd1 = a1x * d4.x + a1y * d4.y + a1z * d4.z + a1w * d4.w;
#pragma unroll
            for (int o = 8; o; o >>= 1) {
                ps0 += __shfl_xor_sync(0xffffffffu, ps0, o);
                pd0 += __shfl_xor_sync(0xffffffffu, pd0, o);
                ps1 += __shfl_xor_sync(0xffffffffu, ps1, o);
                pd1 += __shfl_xor_sync(0xffffffffu, pd1, o);
            }
            if (cg == 0) {
                g_as[tile * 32 + r0] = ps0;
                g_ad[tile * 32 + r0] = pd0;
                g_as[tile * 32 + r1] = ps1;
                g_ad[tile * 32 + r1] = pd1;
            }
        }
        __syncthreads();
    }
}

// ------------------------------ GAT aggregate -------------------------------
// One warp per destination node. Two-pass segment softmax using CSR; h gathers
// coalesced across the 64 features (two 128B loads/edge). Self-loop handled
// inline (never stored in CSR).
__global__ void k_agg(const float* __restrict__ h, const float* __restrict__ bias,
                      float* __restrict__ out, int relu) {
    int gw = (blockIdx.x * blockDim.x + threadIdx.x) >> 5;
    int lane = threadIdx.x & 31;
    if (gw >= NNODES) return;
    int beg = g_off[gw], end = g_off[gw + 1];
    float adv = g_ad[gw];
    float eself = lrelu(g_as[gw] + adv);

    float m = eself;
    for (int i = beg + lane; i < end; i += 32) {
        int s = g_csr_src[i];
        m = fmaxf(m, lrelu(g_as[s] + adv));
    }
#pragma unroll
    for (int o = 16; o; o >>= 1) m = fmaxf(m, __shfl_xor_sync(0xffffffffu, m, o));

    float ws = __expf(eself - m);
    float denom = ws;
    float acc0 = ws * __ldg(&h[(size_t)gw * 64 + lane]);
    float acc1 = ws * __ldg(&h[(size_t)gw * 64 + 32 + lane]);

    int i = beg;
    for (; i + 1 < end; i += 2) {
        int s0 = g_csr_src[i], s1 = g_csr_src[i + 1];
        float w0 = __expf(lrelu(g_as[s0] + adv) - m);
        float w1 = __expf(lrelu(g_as[s1] + adv) - m);
        denom += w0 + w1;
        acc0 += w0 * __ldg(&h[(size_t)s0 * 64 + lane]);
        acc1 += w0 * __ldg(&h[(size_t)s0 * 64 + 32 + lane]);
        acc0 += w1 * __ldg(&h[(size_t)s1 * 64 + lane]);
        acc1 += w1 * __ldg(&h[(size_t)s1 * 64 + 32 + lane]);
    }
    if (i < end) {
        int s0 = g_csr_src[i];
        float w0 = __expf(lrelu(g_as[s0] + adv) - m);
        denom += w0;
        acc0 += w0 * __ldg(&h[(size_t)s0 * 64 + lane]);
        acc1 += w0 * __ldg(&h[(size_t)s0 * 64 + 32 + lane]);
    }
    float inv = 1.0f / (denom + 1e-16f);
    float o0 = acc0 * inv + bias[lane];
    float o1 = acc1 * inv + bias[lane + 32];
    if (relu) { o0 = fmaxf(o0, 0.f); o1 = fmaxf(o1, 0.f); }
    out[(size_t)gw * 64 + lane] = o0;
    out[(size_t)gw * 64 + 32 + lane] = o1;
}

// ------------------------------ log_softmax ---------------------------------
__global__ void k_lsm(const float* __restrict__ logits, float* __restrict__ out) {
    int n = (blockIdx.x * blockDim.x + threadIdx.x) >> 5;
    int lane = threadIdx.x & 31;
    if (n >= NNODES) return;
    float v0 = logits[(size_t)n * NCLS + lane];
    float v1 = (lane < 8) ? logits[(size_t)n * NCLS + 32 + lane] : -1e30f;
    float m = fmaxf(v0, v1);
#pragma unroll
    for (int o = 16; o; o >>= 1) m = fmaxf(m, __shfl_xor_sync(0xffffffffu, m, o));
    float s = __expf(v0 - m) + ((lane < 8) ? __expf(v1 - m) : 0.f);
#pragma unroll
    for (int o = 16; o; o >>= 1) s += __shfl_xor_sync(0xffffffffu, s, o);
    float lse = m + logf(s);
    out[(size_t)n * NCLS + lane] = v0 - lse;
    if (lane < 8) out[(size_t)n * NCLS + 32 + lane] = v1 - lse;
}

// ------------------------------ launch --------------------------------------
extern "C" void kernel_launch(void* const* d_in, const int* in_sizes, int n_in,
                              void* d_out, int out_size) {
    const float* x    = (const float*)d_in[0];
    const void*  ei   = d_in[1];
    const float* W1   = (const float*)d_in[2];
    const float* b1   = (const float*)d_in[3];
    const float* Wc0  = (const float*)d_in[4];
    const float* as0  = (const float*)d_in[5];
    const float* ad0  = (const float*)d_in[6];
    const float* bi0  = (const float*)d_in[7];
    const float* Wc1  = (const float*)d_in[8];
    const float* as1  = (const float*)d_in[9];
    const float* ad1  = (const float*)d_in[10];
    const float* bi1  = (const float*)d_in[11];
    const float* W2   = (const float*)d_in[12];
    const float* b2   = (const float*)d_in[13];
    float*       outp = (float*)d_out;

    int E = in_sizes[1] / 2;
    if (E > EMAX) E = EMAX;

    float *pA = nullptr, *pB = nullptr;
    cudaGetSymbolAddress((void**)&pA, g_bufA);
    cudaGetSymbolAddress((void**)&pB, g_bufB);

    // dtype detect + normalize edges to int32
    k_detect<<<1, 256>>>((const int*)ei, in_sizes[1]);
    k_convert<<<(2 * E + 255) / 256, 256>>>(ei, E);

    // CSR build
    k_zero_deg<<<(NNODES + 255) / 256, 256>>>();
    k_hist<<<(E + 255) / 256, 256>>>(E);
    int nb = (NNODES + 1023) / 1024;
    k_scan1<<<nb, 1024>>>();
    k_scan2<<<1, 32>>>(nb);
    k_scan3<<<nb, 1024>>>();
    k_scatter<<<(E + 255) / 256, 256>>>(E);

    const int GGRID = 1184;
    // h1 = relu(x @ W1 + b1)
    {
        size_t sm = (size_t)(FIN * 64 + 32 * FIN) * 4;
        k_gemm<FIN, HID, false, true, true><<<GGRID, 256, sm>>>(
            x, W1, b1, nullptr, nullptr, pA);
    }
    // hc0 = h1 @ Wc0 ; attention dots
    {
        size_t sm = (size_t)(HID * 64 + 32 * HID) * 4 + 512;
        k_gemm<HID, HID, true, false, false><<<GGRID, 256, sm>>>(
            pA, Wc0, nullptr, as0, ad0, pB);
    }
    k_agg<<<(NNODES * 32 + 255) / 256, 256>>>(pB, bi0, pA, 1);
    // hc1 = g0 @ Wc1 ; attention dots
    {
        size_t sm = (size_t)(HID * 64 + 32 * HID) * 4 + 512;
        k_gemm<HID, HID, true, false, false><<<GGRID, 256, sm>>>(
            pA, Wc1, nullptr, as1, ad1, pB);
    }
    k_agg<<<(NNODES * 32 + 255) / 256, 256>>>(pB, bi1, pA, 0);
    // logits = g1 @ W2 + b2
    {
        size_t sm = (size_t)(HID * 64 + 32 * HID) * 4;
        k_gemm<HID, NCLS, false, true, false><<<GGRID, 256, sm>>>(
            pA, W2, b2, nullptr, nullptr, pB);
    }
    k_lsm<<<(NNODES * 32 + 255) / 256, 256>>>(pB, outp);
}

// round 4
// speedup vs baseline: 1.0514x; 1.0514x over previous
#include <cuda_runtime.h>
#include <cstdint>

#define NNODES 100000
#define EMAX   1700000
#define HID    64
#define FIN    128
#define NCLS   40

// ------------------------------ device scratch ------------------------------
__device__ float g_bufA[NNODES * HID];
__device__ float g_bufB[NNODES * HID];
__device__ float g_as[NNODES];
__device__ float g_ad[NNODES];
__device__ int   g_deg[NNODES];
__device__ int   g_off[NNODES + 1];
__device__ int   g_pos[NNODES];
__device__ int   g_csr_src[EMAX];
__device__ int   g_esrc[EMAX];
__device__ int   g_edst[EMAX];
__device__ int   g_bsum[128];
__device__ int   g_boff[128];
__device__ int   g_idx32;

__device__ __forceinline__ float lrelu(float x) { return x > 0.f ? x : 0.2f * x; }

#define FMA2(d, a, b) asm("fma.rn.f32x2 %0, %1, %2, %0;" : "+l"(d) : "l"(a), "l"(b))
#define DUP2(d, f)    asm("mov.b64 %0, {%1, %1};" : "=l"(d) : "f"(f))

__device__ __forceinline__ float f2lo(unsigned long long v) {
    return __uint_as_float((unsigned)(v & 0xffffffffu));
}
__device__ __forceinline__ float f2hi(unsigned long long v) {
    return __uint_as_float((unsigned)(v >> 32));
}

// ------------------------------ dtype detect + convert ----------------------
__global__ void k_detect(const int* __restrict__ w, int nwords) {
    __shared__ int nz;
    if (threadIdx.x == 0) nz = 0;
    __syncthreads();
    int n = nwords < 4096 ? nwords : 4096;
    int found = 0;
    for (int i = 2 * threadIdx.x + 1; i < n; i += 2 * blockDim.x)
        if (w[i] != 0) found = 1;
    if (found) atomicExch(&nz, 1);
    __syncthreads();
    if (threadIdx.x == 0) g_idx32 = nz;
}

__global__ void k_zero_deg() {
    int i = blockIdx.x * blockDim.x + threadIdx.x;
    if (i < NNODES) g_deg[i] = 0;
}

// convert to int32 + histogram destinations in one pass
__global__ void k_convert_hist(const void* __restrict__ ei, int E) {
    int e = blockIdx.x * blockDim.x + threadIdx.x;
    if (e >= E) return;
    int s, d;
    if (g_idx32) {
        const int* p = (const int*)ei;
        s = p[e]; d = p[E + e];
    } else {
        const long long* p = (const long long*)ei;
        s = (int)p[e]; d = (int)p[E + e];
    }
    g_esrc[e] = s;
    g_edst[e] = d;
    atomicAdd(&g_deg[d], 1);
}

// ------------------------------ scan + scatter ------------------------------
__global__ void k_scan1() {
    __shared__ int sh[1024];
    int i = blockIdx.x * 1024 + threadIdx.x;
    int v = (i < NNODES) ? g_deg[i] : 0;
    sh[threadIdx.x] = v;
    __syncthreads();
    for (int o = 1; o < 1024; o <<= 1) {
        int t = 0;
        if (threadIdx.x >= o) t = sh[threadIdx.x - o];
        __syncthreads();
        sh[threadIdx.x] += t;
        __syncthreads();
    }
    if (i < NNODES) g_pos[i] = sh[threadIdx.x];
    if (threadIdx.x == 1023) g_bsum[blockIdx.x] = sh[1023];
}

__global__ void k_scan2(int nb) {
    if (threadIdx.x == 0 && blockIdx.x == 0) {
        int run = 0;
        for (int b = 0; b < nb; b++) { g_boff[b] = run; run += g_bsum[b]; }
    }
}

__global__ void k_scan3() {
    int i = blockIdx.x * 1024 + threadIdx.x;
    if (i < NNODES) {
        int incl = g_pos[i] + g_boff[blockIdx.x];
        int excl = incl - g_deg[i];
        g_off[i] = excl;
        g_pos[i] = excl;
        if (i == NNODES - 1) g_off[NNODES] = incl;
    }
}

__global__ void k_scatter(int E) {
    int e = blockIdx.x * blockDim.x + threadIdx.x;
    if (e < E) {
        int d = g_edst[e];
        int p = atomicAdd(&g_pos[d], 1);
        g_csr_src[p] = g_esrc[e];
    }
}

// ------------------------------ GEMM (FFMA2) --------------------------------
// 64-row tile, 256 threads, each thread 4 rows x 4 cols, packed f32x2 FMAs.
// sXT: [K][64] k-major/row-minor (transposed); sW: [K][64] (cols padded).
template <int K, int NC, bool ATT, bool BIAS, bool RELU>
__global__ void k_gemm(const float* __restrict__ X, const float* __restrict__ Wg,
                       const float* __restrict__ bias,
                       const float* __restrict__ attS, const float* __restrict__ attD,
                       float* __restrict__ out) {
    extern __shared__ float smem[];
    float* sW  = smem;               // [K][64]
    float* sXT = smem + K * 64;      // [K][64]
    float* sAS = sXT + K * 64;       // [64] if ATT
    float* sAD = sAS + 64;

    for (int i = threadIdx.x; i < K * 64; i += 256) sW[i] = 0.f;
    if (ATT) {
        for (int i = threadIdx.x; i < 64; i += 256) {
            sAS[i] = (i < NC) ? attS[i] : 0.f;
            sAD[i] = (i < NC) ? attD[i] : 0.f;
        }
    }
    __syncthreads();
    for (int i = threadIdx.x; i < K * NC; i += 256)
        sW[(i / NC) * 64 + (i % NC)] = Wg[i];

    // load X tile transposed: unit = one float4 (4 k's of one row)
    const int base = blockIdx.x * 64;
    const int units = 16 * K;        // 64 * K/4
    for (int u = threadIdx.x; u < units; u += 256) {
        int row = u & 63;
        int kq  = u >> 6;
        int gr = base + row;
        float4 v = make_float4(0.f, 0.f, 0.f, 0.f);
        if (gr < NNODES) v = *(const float4*)&X[(size_t)gr * K + kq * 4];
        sXT[(kq * 4 + 0) * 64 + row] = v.x;
        sXT[(kq * 4 + 1) * 64 + row] = v.y;
        sXT[(kq * 4 + 2) * 64 + row] = v.z;
        sXT[(kq * 4 + 3) * 64 + row] = v.w;
    }
    __syncthreads();

    const int cg = threadIdx.x & 15;   // 4 cols: cg*4..+3
    const int rg = threadIdx.x >> 4;   // 4 rows: rg*4..+3

    unsigned long long acc[4][2];
#pragma unroll
    for (int r = 0; r < 4; r++) { acc[r][0] = 0ull; acc[r][1] = 0ull; }

#pragma unroll 8
    for (int k = 0; k < K; k++) {
        float4  xv = *(const float4*)&sXT[k * 64 + rg * 4];
        double2 wd = *(const double2*)&sW[k * 64 + cg * 4];
        unsigned long long w01 = __double_as_longlong(wd.x);
        unsigned long long w23 = __double_as_longlong(wd.y);
        unsigned long long x0, x1, x2, x3;
        DUP2(x0, xv.x); DUP2(x1, xv.y); DUP2(x2, xv.z); DUP2(x3, xv.w);
        FMA2(acc[0][0], x0, w01); FMA2(acc[0][1], x0, w23);
        FMA2(acc[1][0], x1, w01); FMA2(acc[1][1], x1, w23);
        FMA2(acc[2][0], x2, w01); FMA2(acc[2][1], x2, w23);
        FMA2(acc[3][0], x3, w01); FMA2(acc[3][1], x3, w23);
    }

    const int c = cg * 4;
#pragma unroll
    for (int r = 0; r < 4; r++) {
        int gr = base + rg * 4 + r;
        float4 o;
        o.x = f2lo(acc[r][0]); o.y = f2hi(acc[r][0]);
        o.z = f2lo(acc[r][1]); o.w = f2hi(acc[r][1]);

        if (ATT) {
            float ps = o.x * sAS[c] + o.y * sAS[c + 1] + o.z * sAS[c + 2] + o.w * sAS[c + 3];
            float pd = o.x * sAD[c] + o.y * sAD[c + 1] + o.z * sAD[c + 2] + o.w * sAD[c + 3];
#pragma unroll
            for (int off = 8; off; off >>= 1) {
                ps += __shfl_xor_sync(0xffffffffu, ps, off);
                pd += __shfl_xor_sync(0xffffffffu, pd, off);
            }
            if (cg == 0 && gr < NNODES) { g_as[gr] = ps; g_ad[gr] = pd; }
        }

        if (c < NC && gr < NNODES) {
            if (BIAS) {
                o.x += bias[c]; o.y += bias[c + 1]; o.z += bias[c + 2]; o.w += bias[c + 3];
            }
            if (RELU) {
                o.x = fmaxf(o.x, 0.f); o.y = fmaxf(o.y, 0.f);
                o.z = fmaxf(o.z, 0.f); o.w = fmaxf(o.w, 0.f);
            }
            *(float4*)&out[(size_t)gr * NC + c] = o;
        }
    }
}

// ------------------------------ GAT aggregate -------------------------------
__global__ void k_agg(const float* __restrict__ h, const float* __restrict__ bias,
                      float* __restrict__ out, int relu) {
    int gw = (blockIdx.x * blockDim.x + threadIdx.x) >> 5;
    int lane = threadIdx.x & 31;
    if (gw >= NNODES) return;
    int beg = g_off[gw], end = g_off[gw + 1];
    float adv = g_ad[gw];
    float as_self = g_as[gw];

    // max over raw a_s (lrelu is monotone)
    float mr = as_self;
    for (int i = beg + lane; i < end; i += 32)
        mr = fmaxf(mr, g_as[g_csr_src[i]]);
#pragma unroll
    for (int o = 16; o; o >>= 1) mr = fmaxf(mr, __shfl_xor_sync(0xffffffffu, mr, o));
    float m = lrelu(mr + adv);

    float ws = __expf(lrelu(as_self + adv) - m);
    float denom = ws;
    float acc0 = ws * __ldg(&h[(size_t)gw * 64 + lane]);
    float acc1 = ws * __ldg(&h[(size_t)gw * 64 + 32 + lane]);

    int i = beg;
    for (; i + 1 < end; i += 2) {
        int s0 = g_csr_src[i], s1 = g_csr_src[i + 1];
        float w0 = __expf(lrelu(g_as[s0] + adv) - m);
        float w1 = __expf(lrelu(g_as[s1] + adv) - m);
        denom += w0 + w1;
        acc0 += w0 * __ldg(&h[(size_t)s0 * 64 + lane]);
        acc1 += w0 * __ldg(&h[(size_t)s0 * 64 + 32 + lane]);
        acc0 += w1 * __ldg(&h[(size_t)s1 * 64 + lane]);
        acc1 += w1 * __ldg(&h[(size_t)s1 * 64 + 32 + lane]);
    }
    if (i < end) {
        int s0 = g_csr_src[i];
        float w0 = __expf(lrelu(g_as[s0] + adv) - m);
        denom += w0;
        acc0 += w0 * __ldg(&h[(size_t)s0 * 64 + lane]);
        acc1 += w0 * __ldg(&h[(size_t)s0 * 64 + 32 + lane]);
    }
    float inv = 1.0f / (denom + 1e-16f);
    float o0 = acc0 * inv + bias[lane];
    float o1 = acc1 * inv + bias[lane + 32];
    if (relu) { o0 = fmaxf(o0, 0.f); o1 = fmaxf(o1, 0.f); }
    out[(size_t)gw * 64 + lane] = o0;
    out[(size_t)gw * 64 + 32 + lane] = o1;
}

// ------------------------------ log_softmax ---------------------------------
__global__ void k_lsm(const float* __restrict__ logits, float* __restrict__ out) {
    int n = (blockIdx.x * blockDim.x + threadIdx.x) >> 5;
    int lane = threadIdx.x & 31;
    if (n >= NNODES) return;
    float v0 = logits[(size_t)n * NCLS + lane];
    float v1 = (lane < 8) ? logits[(size_t)n * NCLS + 32 + lane] : -1e30f;
    float m = fmaxf(v0, v1);
#pragma unroll
    for (int o = 16; o; o >>= 1) m = fmaxf(m, __shfl_xor_sync(0xffffffffu, m, o));
    float s = __expf(v0 - m) + ((lane < 8) ? __expf(v1 - m) : 0.f);
#pragma unroll
    for (int o = 16; o; o >>= 1) s += __shfl_xor_sync(0xffffffffu, s, o);
    float lse = m + logf(s);
    out[(size_t)n * NCLS + lane] = v0 - lse;
    if (lane < 8) out[(size_t)n * NCLS + 32 + lane] = v1 - lse;
}

// ------------------------------ launch --------------------------------------
extern "C" void kernel_launch(void* const* d_in, const int* in_sizes, int n_in,
                              void* d_out, int out_size) {
    const float* x    = (const float*)d_in[0];
    const void*  ei   = d_in[1];
    const float* W1   = (const float*)d_in[2];
    const float* b1   = (const float*)d_in[3];
    const float* Wc0  = (const float*)d_in[4];
    const float* as0  = (const float*)d_in[5];
    const float* ad0  = (const float*)d_in[6];
    const float* bi0  = (const float*)d_in[7];
    const float* Wc1  = (const float*)d_in[8];
    const float* as1  = (const float*)d_in[9];
    const float* ad1  = (const float*)d_in[10];
    const float* bi1  = (const float*)d_in[11];
    const float* W2   = (const float*)d_in[12];
    const float* b2   = (const float*)d_in[13];
    float*       outp = (float*)d_out;

    int E = in_sizes[1] / 2;
    if (E > EMAX) E = EMAX;

    float *pA = nullptr, *pB = nullptr;
    cudaGetSymbolAddress((void**)&pA, g_bufA);
    cudaGetSymbolAddress((void**)&pB, g_bufB);

    // one-time (idempotent) smem opt-in for the K=128 GEMM (64KB dynamic)
    cudaFuncSetAttribute(k_gemm<FIN, HID, false, true, true>,
                         cudaFuncAttributeMaxDynamicSharedMemorySize, 2 * FIN * 64 * 4);

    k_detect<<<1, 256>>>((const int*)ei, in_sizes[1]);
    k_zero_deg<<<(NNODES + 255) / 256, 256>>>();
    k_convert_hist<<<(E + 255) / 256, 256>>>(ei, E);
    int nb = (NNODES + 1023) / 1024;
    k_scan1<<<nb, 1024>>>();
    k_scan2<<<1, 32>>>(nb);
    k_scan3<<<nb, 1024>>>();
    k_scatter<<<(E + 255) / 256, 256>>>(E);

    const int NTILES = (NNODES + 63) / 64;
    // h1 = relu(x @ W1 + b1)
    {
        size_t sm = (size_t)(2 * FIN * 64) * 4;
        k_gemm<FIN, HID, false, true, true><<<NTILES, 256, sm>>>(
            x, W1, b1, nullptr, nullptr, pA);
    }
    // hc0 = h1 @ Wc0 ; attention dots
    {
        size_t sm = (size_t)(2 * HID * 64 + 128) * 4;
        k_gemm<HID, HID, true, false, false><<<NTILES, 256, sm>>>(
            pA, Wc0, nullptr, as0, ad0, pB);
    }
    k_agg<<<(NNODES * 32 + 255) / 256, 256>>>(pB, bi0, pA, 1);
    // hc1 = g0 @ Wc1 ; attention dots
    {
        size_t sm = (size_t)(2 * HID * 64 + 128) * 4;
        k_gemm<HID, HID, true, false, false><<<NTILES, 256, sm>>>(
            pA, Wc1, nullptr, as1, ad1, pB);
    }
    k_agg<<<(NNODES * 32 + 255) / 256, 256>>>(pB, bi1, pA, 0);
    // logits = g1 @ W2 + b2
    {
        size_t sm = (size_t)(2 * HID * 64) * 4;
        k_gemm<HID, NCLS, false, true, false><<<NTILES, 256, sm>>>(
            pA, W2, b2, nullptr, nullptr, pB);
    }
    k_lsm<<<(NNODES * 32 + 255) / 256, 256>>>(pB, outp);
}

// round 5
// speedup vs baseline: 1.0944x; 1.0409x over previous
#include <cuda_runtime.h>
#include <cstdint>

#define NNODES 100000
#define EMAX   1700000
#define HID    64
#define FIN    128
#define NCLS   40

// ------------------------------ device scratch ------------------------------
__device__ float g_bufA[NNODES * HID];
__device__ float g_bufB[NNODES * HID];
__device__ float g_as[NNODES];
__device__ float g_ad[NNODES];
__device__ int   g_deg[NNODES];
__device__ int   g_off[NNODES + 1];
__device__ int   g_pos[NNODES];
__device__ int   g_csr_src[EMAX];
__device__ int   g_esrc[EMAX];
__device__ int   g_edst[EMAX];
__device__ int   g_bsum[128];
__device__ int   g_boff[128];
__device__ int   g_idx32;
__device__ unsigned g_mxu[4];       // ordered-encoded float maxima, 2 per layer

__device__ __forceinline__ float lrelu(float x) { return x > 0.f ? x : 0.2f * x; }

__device__ __forceinline__ unsigned fenc(float f) {
    unsigned u = __float_as_uint(f);
    return (u & 0x80000000u) ? ~u : (u | 0x80000000u);
}
__device__ __forceinline__ float fdec(unsigned k) {
    return (k & 0x80000000u) ? __uint_as_float(k & 0x7fffffffu)
                             : __uint_as_float(~k);
}

#define FMA2(d, a, b) asm("fma.rn.f32x2 %0, %1, %2, %0;" : "+l"(d) : "l"(a), "l"(b))
#define DUP2(d, f)    asm("mov.b64 %0, {%1, %1};" : "=l"(d) : "f"(f))

__device__ __forceinline__ float f2lo(unsigned long long v) {
    return __uint_as_float((unsigned)(v & 0xffffffffu));
}
__device__ __forceinline__ float f2hi(unsigned long long v) {
    return __uint_as_float((unsigned)(v >> 32));
}

// --------------------- init: zero deg, reset maxima, detect dtype -----------
__global__ void k_init(const int* __restrict__ w, int nwords) {
    __shared__ int nz;
    int i = blockIdx.x * blockDim.x + threadIdx.x;
    if (i < NNODES) g_deg[i] = 0;
    if (i < 4) g_mxu[i] = 0u;
    if (blockIdx.x == 0) {
        if (threadIdx.x == 0) nz = 0;
        __syncthreads();
        int n = nwords < 4096 ? nwords : 4096;
        int found = 0;
        for (int j = 2 * threadIdx.x + 1; j < n; j += 2 * blockDim.x)
            if (w[j] != 0) found = 1;
        if (found) atomicExch(&nz, 1);
        __syncthreads();
        if (threadIdx.x == 0) g_idx32 = nz;
    }
}

// convert to int32 + histogram destinations in one pass
__global__ void k_convert_hist(const void* __restrict__ ei, int E) {
    int e = blockIdx.x * blockDim.x + threadIdx.x;
    if (e >= E) return;
    int s, d;
    if (g_idx32) {
        const int* p = (const int*)ei;
        s = p[e]; d = p[E + e];
    } else {
        const long long* p = (const long long*)ei;
        s = (int)p[e]; d = (int)p[E + e];
    }
    g_esrc[e] = s;
    g_edst[e] = d;
    atomicAdd(&g_deg[d], 1);
}

// ------------------------------ scan + scatter ------------------------------
__global__ void k_scan1() {
    __shared__ int sh[1024];
    int i = blockIdx.x * 1024 + threadIdx.x;
    int v = (i < NNODES) ? g_deg[i] : 0;
    sh[threadIdx.x] = v;
    __syncthreads();
    for (int o = 1; o < 1024; o <<= 1) {
        int t = 0;
        if (threadIdx.x >= o) t = sh[threadIdx.x - o];
        __syncthreads();
        sh[threadIdx.x] += t;
        __syncthreads();
    }
    if (i < NNODES) g_pos[i] = sh[threadIdx.x];
    if (threadIdx.x == 1023) g_bsum[blockIdx.x] = sh[1023];
}

__global__ void k_scan2(int nb) {
    if (threadIdx.x == 0 && blockIdx.x == 0) {
        int run = 0;
        for (int b = 0; b < nb; b++) { g_boff[b] = run; run += g_bsum[b]; }
    }
}

__global__ void k_scan3() {
    int i = blockIdx.x * 1024 + threadIdx.x;
    if (i < NNODES) {
        int incl = g_pos[i] + g_boff[blockIdx.x];
        int excl = incl - g_deg[i];
        g_off[i] = excl;
        g_pos[i] = excl;
        if (i == NNODES - 1) g_off[NNODES] = incl;
    }
}

__global__ void k_scatter(int E) {
    int e = blockIdx.x * blockDim.x + threadIdx.x;
    if (e < E) {
        int d = g_edst[e];
        int p = atomicAdd(&g_pos[d], 1);
        g_csr_src[p] = g_esrc[e];
    }
}

// ------------------------------ global max of a_s / a_d ---------------------
__global__ void k_max(int slot) {
    float ma = -1e30f, md = -1e30f;
    for (int i = blockIdx.x * blockDim.x + threadIdx.x; i < NNODES;
         i += gridDim.x * blockDim.x) {
        ma = fmaxf(ma, g_as[i]);
        md = fmaxf(md, g_ad[i]);
    }
#pragma unroll
    for (int o = 16; o; o >>= 1) {
        ma = fmaxf(ma, __shfl_xor_sync(0xffffffffu, ma, o));
        md = fmaxf(md, __shfl_xor_sync(0xffffffffu, md, o));
    }
    __shared__ float sa[32], sd[32];
    int w = threadIdx.x >> 5, l = threadIdx.x & 31;
    if (l == 0) { sa[w] = ma; sd[w] = md; }
    __syncthreads();
    if (w == 0) {
        int nw = blockDim.x >> 5;
        ma = (l < nw) ? sa[l] : -1e30f;
        md = (l < nw) ? sd[l] : -1e30f;
#pragma unroll
        for (int o = 16; o; o >>= 1) {
            ma = fmaxf(ma, __shfl_xor_sync(0xffffffffu, ma, o));
            md = fmaxf(md, __shfl_xor_sync(0xffffffffu, md, o));
        }
        if (l == 0) {
            atomicMax(&g_mxu[slot * 2],     fenc(ma));
            atomicMax(&g_mxu[slot * 2 + 1], fenc(md));
        }
    }
}

// ------------------------------ GEMM (FFMA2) --------------------------------
template <int K, int NC, bool ATT, bool BIAS, bool RELU, bool LSM>
__global__ void k_gemm(const float* __restrict__ X, const float* __restrict__ Wg,
                       const float* __restrict__ bias,
                       const float* __restrict__ attS, const float* __restrict__ attD,
                       float* __restrict__ out) {
    extern __shared__ float smem[];
    float* sW  = smem;               // [K][64]
    float* sXT = smem + K * 64;      // [K][64]
    float* sAS = sXT + K * 64;       // [64] if ATT
    float* sAD = sAS + 64;

    for (int i = threadIdx.x; i < K * 64; i += 256) sW[i] = 0.f;
    if (ATT) {
        for (int i = threadIdx.x; i < 64; i += 256) {
            sAS[i] = (i < NC) ? attS[i] : 0.f;
            sAD[i] = (i < NC) ? attD[i] : 0.f;
        }
    }
    __syncthreads();
    for (int i = threadIdx.x; i < K * NC; i += 256)
        sW[(i / NC) * 64 + (i % NC)] = Wg[i];

    const int base = blockIdx.x * 64;
    const int units = 16 * K;
    for (int u = threadIdx.x; u < units; u += 256) {
        int row = u & 63;
        int kq  = u >> 6;
        int gr = base + row;
        float4 v = make_float4(0.f, 0.f, 0.f, 0.f);
        if (gr < NNODES) v = *(const float4*)&X[(size_t)gr * K + kq * 4];
        sXT[(kq * 4 + 0) * 64 + row] = v.x;
        sXT[(kq * 4 + 1) * 64 + row] = v.y;
        sXT[(kq * 4 + 2) * 64 + row] = v.z;
        sXT[(kq * 4 + 3) * 64 + row] = v.w;
    }
    __syncthreads();

    const int cg = threadIdx.x & 15;
    const int rg = threadIdx.x >> 4;

    unsigned long long acc[4][2];
#pragma unroll
    for (int r = 0; r < 4; r++) { acc[r][0] = 0ull; acc[r][1] = 0ull; }

#pragma unroll 8
    for (int k = 0; k < K; k++) {
        float4  xv = *(const float4*)&sXT[k * 64 + rg * 4];
        double2 wd = *(const double2*)&sW[k * 64 + cg * 4];
        unsigned long long w01 = __double_as_longlong(wd.x);
        unsigned long long w23 = __double_as_longlong(wd.y);
        unsigned long long x0, x1, x2, x3;
        DUP2(x0, xv.x); DUP2(x1, xv.y); DUP2(x2, xv.z); DUP2(x3, xv.w);
        FMA2(acc[0][0], x0, w01); FMA2(acc[0][1], x0, w23);
        FMA2(acc[1][0], x1, w01); FMA2(acc[1][1], x1, w23);
        FMA2(acc[2][0], x2, w01); FMA2(acc[2][1], x2, w23);
        FMA2(acc[3][0], x3, w01); FMA2(acc[3][1], x3, w23);
    }

    const int c = cg * 4;
#pragma unroll
    for (int r = 0; r < 4; r++) {
        int gr = base + rg * 4 + r;
        float4 o;
        o.x = f2lo(acc[r][0]); o.y = f2hi(acc[r][0]);
        o.z = f2lo(acc[r][1]); o.w = f2hi(acc[r][1]);

        if (ATT) {
            float ps = o.x * sAS[c] + o.y * sAS[c + 1] + o.z * sAS[c + 2] + o.w * sAS[c + 3];
            float pd = o.x * sAD[c] + o.y * sAD[c + 1] + o.z * sAD[c + 2] + o.w * sAD[c + 3];
#pragma unroll
            for (int off = 8; off; off >>= 1) {
                ps += __shfl_xor_sync(0xffffffffu, ps, off);
                pd += __shfl_xor_sync(0xffffffffu, pd, off);
            }
            if (cg == 0 && gr < NNODES) { g_as[gr] = ps; g_ad[gr] = pd; }
        }

        if (BIAS && c < NC) {
            o.x += bias[c]; o.y += bias[c + 1]; o.z += bias[c + 2]; o.w += bias[c + 3];
        }

        if (LSM) {
            // row-wise log_softmax over NC cols, held by 16-lane group
            float lm = -1e30f;
            if (c < NC) lm = fmaxf(fmaxf(o.x, o.y), fmaxf(o.z, o.w));
#pragma unroll
            for (int off = 8; off; off >>= 1)
                lm = fmaxf(lm, __shfl_xor_sync(0xffffffffu, lm, off, 16));
            float le = 0.f;
            if (c < NC)
                le = __expf(o.x - lm) + __expf(o.y - lm) + __expf(o.z - lm) + __expf(o.w - lm);
#pragma unroll
            for (int off = 8; off; off >>= 1)
                le += __shfl_xor_sync(0xffffffffu, le, off, 16);
            float lse = lm + __logf(le);
            if (c < NC && gr < NNODES) {
                o.x -= lse; o.y -= lse; o.z -= lse; o.w -= lse;
                *(float4*)&out[(size_t)gr * NC + c] = o;
            }
        } else if (c < NC && gr < NNODES) {
            if (RELU) {
                o.x = fmaxf(o.x, 0.f); o.y = fmaxf(o.y, 0.f);
                o.z = fmaxf(o.z, 0.f); o.w = fmaxf(o.w, 0.f);
            }
            *(float4*)&out[(size_t)gr * NC + c] = o;
        }
    }
}

// ------------------------------ GAT aggregate -------------------------------
// Warp per dst node. Lane-parallel weight phase (coalesced csr + parallel
// exp), then broadcast loop with unrolled coalesced h gathers. Global softmax
// shift m (valid: softmax is shift-invariant; bound keeps exp in range).
__global__ void k_agg(const float* __restrict__ h, const float* __restrict__ bias,
                      float* __restrict__ out, int relu, int slot) {
    int gw = (blockIdx.x * blockDim.x + threadIdx.x) >> 5;
    int lane = threadIdx.x & 31;
    if (gw >= NNODES) return;
    int beg = g_off[gw], end = g_off[gw + 1];
    float adv = g_ad[gw];
    float m = lrelu(fdec(g_mxu[slot * 2]) + fdec(g_mxu[slot * 2 + 1]));

    float wself = __expf(lrelu(g_as[gw] + adv) - m);
    float dsum = (lane == 0) ? wself : 0.f;
    float acc0 = wself * __ldg(&h[(size_t)gw * 64 + lane]);
    float acc1 = wself * __ldg(&h[(size_t)gw * 64 + 32 + lane]);

    for (int chunk = beg; chunk < end; chunk += 32) {
        int idx = chunk + lane;
        int s = 0; float w = 0.f;
        if (idx < end) {
            s = g_csr_src[idx];
            w = __expf(lrelu(g_as[s] + adv) - m);
        }
        dsum += w;
        int cnt = end - chunk;
        if (cnt >= 32) {
#pragma unroll 4
            for (int j = 0; j < 32; j++) {
                int   sj = __shfl_sync(0xffffffffu, s, j);
                float wj = __shfl_sync(0xffffffffu, w, j);
                acc0 = fmaf(wj, __ldg(&h[(size_t)sj * 64 + lane]), acc0);
                acc1 = fmaf(wj, __ldg(&h[(size_t)sj * 64 + 32 + lane]), acc1);
            }
        } else {
            for (int j = 0; j < cnt; j++) {
                int   sj = __shfl_sync(0xffffffffu, s, j);
                float wj = __shfl_sync(0xffffffffu, w, j);
                acc0 = fmaf(wj, __ldg(&h[(size_t)sj * 64 + lane]), acc0);
                acc1 = fmaf(wj, __ldg(&h[(size_t)sj * 64 + 32 + lane]), acc1);
            }
        }
    }
#pragma unroll
    for (int o = 16; o; o >>= 1) dsum += __shfl_xor_sync(0xffffffffu, dsum, o);

    float inv = 1.0f / (dsum + 1e-16f);
    float o0 = acc0 * inv + bias[lane];
    float o1 = acc1 * inv + bias[lane + 32];
    if (relu) { o0 = fmaxf(o0, 0.f); o1 = fmaxf(o1, 0.f); }
    out[(size_t)gw * 64 + lane] = o0;
    out[(size_t)gw * 64 + 32 + lane] = o1;
}

// ------------------------------ launch --------------------------------------
extern "C" void kernel_launch(void* const* d_in, const int* in_sizes, int n_in,
                              void* d_out, int out_size) {
    const float* x    = (const float*)d_in[0];
    const void*  ei   = d_in[1];
    const float* W1   = (const float*)d_in[2];
    const float* b1   = (const float*)d_in[3];
    const float* Wc0  = (const float*)d_in[4];
    const float* as0  = (const float*)d_in[5];
    const float* ad0  = (const float*)d_in[6];
    const float* bi0  = (const float*)d_in[7];
    const float* Wc1  = (const float*)d_in[8];
    const float* as1  = (const float*)d_in[9];
    const float* ad1  = (const float*)d_in[10];
    const float* bi1  = (const float*)d_in[11];
    const float* W2   = (const float*)d_in[12];
    const float* b2   = (const float*)d_in[13];
    float*       outp = (float*)d_out;

    int E = in_sizes[1] / 2;
    if (E > EMAX) E = EMAX;

    float *pA = nullptr, *pB = nullptr;
    cudaGetSymbolAddress((void**)&pA, g_bufA);
    cudaGetSymbolAddress((void**)&pB, g_bufB);

    cudaFuncSetAttribute(k_gemm<FIN, HID, false, true, true, false>,
                         cudaFuncAttributeMaxDynamicSharedMemorySize, 2 * FIN * 64 * 4);

    k_init<<<(NNODES + 255) / 256, 256>>>((const int*)ei, in_sizes[1]);
    k_convert_hist<<<(E + 255) / 256, 256>>>(ei, E);
    int nb = (NNODES + 1023) / 1024;
    k_scan1<<<nb, 1024>>>();
    k_scan2<<<1, 32>>>(nb);
    k_scan3<<<nb, 1024>>>();
    k_scatter<<<(E + 255) / 256, 256>>>(E);

    const int NTILES = (NNODES + 63) / 64;
    // h1 = relu(x @ W1 + b1)
    {
        size_t sm = (size_t)(2 * FIN * 64) * 4;
        k_gemm<FIN, HID, false, true, true, false><<<NTILES, 256, sm>>>(
            x, W1, b1, nullptr, nullptr, pA);
    }
    // hc0 = h1 @ Wc0 ; attention dots
    {
        size_t sm = (size_t)(2 * HID * 64 + 128) * 4;
        k_gemm<HID, HID, true, false, false, false><<<NTILES, 256, sm>>>(
            pA, Wc0, nullptr, as0, ad0, pB);
    }
    k_max<<<200, 512>>>(0);
    k_agg<<<(NNODES * 32 + 255) / 256, 256>>>(pB, bi0, pA, 1, 0);
    // hc1 = g0 @ Wc1 ; attention dots
    {
        size_t sm = (size_t)(2 * HID * 64 + 128) * 4;
        k_gemm<HID, HID, true, false, false, false><<<NTILES, 256, sm>>>(
            pA, Wc1, nullptr, as1, ad1, pB);
    }
    k_max<<<200, 512>>>(1);
    k_agg<<<(NNODES * 32 + 255) / 256, 256>>>(pB, bi1, pA, 0, 1);
    // logits = g1 @ W2 + b2, fused log_softmax
    {
        size_t sm = (size_t)(2 * HID * 64) * 4;
        k_gemm<HID, NCLS, false, true, false, true><<<NTILES, 256, sm>>>(
            pA, W2, b2, nullptr, nullptr, outp);
    }
}

// round 6
// speedup vs baseline: 1.1308x; 1.0333x over previous
#include <cuda_runtime.h>
#include <cstdint>

#define NNODES 100000
#define EMAX   1700000
#define HID    64
#define FIN    128
#define NCLS   40

// ------------------------------ device scratch ------------------------------
__device__ float g_bufA[NNODES * HID];
__device__ float g_bufB[NNODES * HID];
__device__ float g_as[NNODES];
__device__ float g_ad[NNODES];
__device__ int   g_deg[NNODES];
__device__ int   g_off[NNODES + 1];
__device__ int   g_pos[NNODES];
__device__ int   g_csr_src[EMAX];
__device__ int   g_esrc[EMAX];
__device__ int   g_edst[EMAX];
__device__ int   g_bsum[128];
__device__ volatile int g_flag[128];
__device__ int   g_idx32;
__device__ unsigned g_mxu[4];       // ordered-encoded float maxima, 2 per layer

__device__ __forceinline__ float lrelu(float x) { return x > 0.f ? x : 0.2f * x; }

__device__ __forceinline__ unsigned fenc(float f) {
    unsigned u = __float_as_uint(f);
    return (u & 0x80000000u) ? ~u : (u | 0x80000000u);
}
__device__ __forceinline__ float fdec(unsigned k) {
    return (k & 0x80000000u) ? __uint_as_float(k & 0x7fffffffu)
                             : __uint_as_float(~k);
}

#define FMA2(d, a, b) asm("fma.rn.f32x2 %0, %1, %2, %0;" : "+l"(d) : "l"(a), "l"(b))
#define DUP2(d, f)    asm("mov.b64 %0, {%1, %1};" : "=l"(d) : "f"(f))

__device__ __forceinline__ float f2lo(unsigned long long v) {
    return __uint_as_float((unsigned)(v & 0xffffffffu));
}
__device__ __forceinline__ float f2hi(unsigned long long v) {
    return __uint_as_float((unsigned)(v >> 32));
}

// --------------------- init: zero deg/flags/maxima, detect dtype ------------
__global__ void k_init(const int* __restrict__ w, int nwords) {
    __shared__ int nz;
    int i = blockIdx.x * blockDim.x + threadIdx.x;
    if (i < NNODES) g_deg[i] = 0;
    if (i < 4) g_mxu[i] = 0u;
    if (i < 128) g_flag[i] = 0;
    if (blockIdx.x == 0) {
        if (threadIdx.x == 0) nz = 0;
        __syncthreads();
        int n = nwords < 4096 ? nwords : 4096;
        int found = 0;
        for (int j = 2 * threadIdx.x + 1; j < n; j += 2 * blockDim.x)
            if (w[j] != 0) found = 1;
        if (found) atomicExch(&nz, 1);
        __syncthreads();
        if (threadIdx.x == 0) g_idx32 = nz;
    }
}

// convert to int32 + histogram destinations in one pass
__global__ void k_convert_hist(const void* __restrict__ ei, int E) {
    int e = blockIdx.x * blockDim.x + threadIdx.x;
    if (e >= E) return;
    int s, d;
    if (g_idx32) {
        const int* p = (const int*)ei;
        s = p[e]; d = p[E + e];
    } else {
        const long long* p = (const long long*)ei;
        s = (int)p[e]; d = (int)p[E + e];
    }
    g_esrc[e] = s;
    g_edst[e] = d;
    atomicAdd(&g_deg[d], 1);
}

// ---------------- single-kernel scan (all 98 blocks resident) ---------------
__global__ void k_scan() {
    __shared__ int sh[1024];
    __shared__ int s_off;
    int bid = blockIdx.x;
    int tid = threadIdx.x;
    int i = bid * 1024 + tid;
    int v = (i < NNODES) ? g_deg[i] : 0;
    sh[tid] = v;
    if (tid == 0) s_off = 0;
    __syncthreads();
    for (int o = 1; o < 1024; o <<= 1) {
        int t = 0;
        if (tid >= o) t = sh[tid - o];
        __syncthreads();
        sh[tid] += t;
        __syncthreads();
    }
    // publish block aggregate
    if (tid == 1023) {
        g_bsum[bid] = sh[1023];
        __threadfence();
        g_flag[bid] = 1;
    }
    // gather predecessor aggregates (grid <= #SMs: no deadlock)
    if (tid < bid) {
        while (g_flag[tid] == 0) { }
        atomicAdd(&s_off, g_bsum[tid]);
    }
    __syncthreads();
    if (i < NNODES) {
        int incl = sh[tid] + s_off;
        int excl = incl - v;
        g_off[i] = excl;
        g_pos[i] = excl;
        if (i == NNODES - 1) g_off[NNODES] = incl;
    }
}

__global__ void k_scatter(int E) {
    int e = blockIdx.x * blockDim.x + threadIdx.x;
    if (e < E) {
        int d = g_edst[e];
        int p = atomicAdd(&g_pos[d], 1);
        g_csr_src[p] = g_esrc[e];
    }
}

// ------------------------------ GEMM (FFMA2) --------------------------------
// 64-row tile, 256 threads, 4x4 per thread, packed f32x2 FMAs.
// ATT: fused attention dots to g_as/g_ad + block-wise global max -> g_mxu.
// LSM: fused row log_softmax.
template <int K, int NC, bool ATT, bool BIAS, bool RELU, bool LSM>
__global__ void k_gemm(const float* __restrict__ X, const float* __restrict__ Wg,
                       const float* __restrict__ bias,
                       const float* __restrict__ attS, const float* __restrict__ attD,
                       float* __restrict__ out, int slot) {
    extern __shared__ float smem[];
    float* sW  = smem;               // [K][64]
    float* sXT = smem + K * 64;      // [K][64]
    float* sAS = sXT + K * 64;       // [64] if ATT
    float* sAD = sAS + 64;
    __shared__ unsigned s_mx[2];

    for (int i = threadIdx.x; i < K * 64; i += 256) sW[i] = 0.f;
    if (ATT) {
        if (threadIdx.x < 2) s_mx[threadIdx.x] = 0u;
        for (int i = threadIdx.x; i < 64; i += 256) {
            sAS[i] = (i < NC) ? attS[i] : 0.f;
            sAD[i] = (i < NC) ? attD[i] : 0.f;
        }
    }
    __syncthreads();
    for (int i = threadIdx.x; i < K * NC; i += 256)
        sW[(i / NC) * 64 + (i % NC)] = Wg[i];

    const int base = blockIdx.x * 64;
    const int units = 16 * K;
    for (int u = threadIdx.x; u < units; u += 256) {
        int row = u & 63;
        int kq  = u >> 6;
        int gr = base + row;
        float4 v = make_float4(0.f, 0.f, 0.f, 0.f);
        if (gr < NNODES) v = *(const float4*)&X[(size_t)gr * K + kq * 4];
        sXT[(kq * 4 + 0) * 64 + row] = v.x;
        sXT[(kq * 4 + 1) * 64 + row] = v.y;
        sXT[(kq * 4 + 2) * 64 + row] = v.z;
        sXT[(kq * 4 + 3) * 64 + row] = v.w;
    }
    __syncthreads();

    const int cg = threadIdx.x & 15;
    const int rg = threadIdx.x >> 4;

    unsigned long long acc[4][2];
#pragma unroll
    for (int r = 0; r < 4; r++) { acc[r][0] = 0ull; acc[r][1] = 0ull; }

#pragma unroll 8
    for (int k = 0; k < K; k++) {
        float4  xv = *(const float4*)&sXT[k * 64 + rg * 4];
        double2 wd = *(const double2*)&sW[k * 64 + cg * 4];
        unsigned long long w01 = __double_as_longlong(wd.x);
        unsigned long long w23 = __double_as_longlong(wd.y);
        unsigned long long x0, x1, x2, x3;
        DUP2(x0, xv.x); DUP2(x1, xv.y); DUP2(x2, xv.z); DUP2(x3, xv.w);
        FMA2(acc[0][0], x0, w01); FMA2(acc[0][1], x0, w23);
        FMA2(acc[1][0], x1, w01); FMA2(acc[1][1], x1, w23);
        FMA2(acc[2][0], x2, w01); FMA2(acc[2][1], x2, w23);
        FMA2(acc[3][0], x3, w01); FMA2(acc[3][1], x3, w23);
    }

    const int c = cg * 4;
#pragma unroll
    for (int r = 0; r < 4; r++) {
        int gr = base + rg * 4 + r;
        float4 o;
        o.x = f2lo(acc[r][0]); o.y = f2hi(acc[r][0]);
        o.z = f2lo(acc[r][1]); o.w = f2hi(acc[r][1]);

        if (ATT) {
            float ps = o.x * sAS[c] + o.y * sAS[c + 1] + o.z * sAS[c + 2] + o.w * sAS[c + 3];
            float pd = o.x * sAD[c] + o.y * sAD[c + 1] + o.z * sAD[c + 2] + o.w * sAD[c + 3];
#pragma unroll
            for (int off = 8; off; off >>= 1) {
                ps += __shfl_xor_sync(0xffffffffu, ps, off);
                pd += __shfl_xor_sync(0xffffffffu, pd, off);
            }
            if (cg == 0 && gr < NNODES) {
                g_as[gr] = ps; g_ad[gr] = pd;
                atomicMax(&s_mx[0], fenc(ps));
                atomicMax(&s_mx[1], fenc(pd));
            }
        }

        if (BIAS && c < NC) {
            o.x += bias[c]; o.y += bias[c + 1]; o.z += bias[c + 2]; o.w += bias[c + 3];
        }

        if (LSM) {
            float lm = -1e30f;
            if (c < NC) lm = fmaxf(fmaxf(o.x, o.y), fmaxf(o.z, o.w));
#pragma unroll
            for (int off = 8; off; off >>= 1)
                lm = fmaxf(lm, __shfl_xor_sync(0xffffffffu, lm, off, 16));
            float le = 0.f;
            if (c < NC)
                le = __expf(o.x - lm) + __expf(o.y - lm) + __expf(o.z - lm) + __expf(o.w - lm);
#pragma unroll
            for (int off = 8; off; off >>= 1)
                le += __shfl_xor_sync(0xffffffffu, le, off, 16);
            float lse = lm + __logf(le);
            if (c < NC && gr < NNODES) {
                o.x -= lse; o.y -= lse; o.z -= lse; o.w -= lse;
                *(float4*)&out[(size_t)gr * NC + c] = o;
            }
        } else if (c < NC && gr < NNODES) {
            if (RELU) {
                o.x = fmaxf(o.x, 0.f); o.y = fmaxf(o.y, 0.f);
                o.z = fmaxf(o.z, 0.f); o.w = fmaxf(o.w, 0.f);
            }
            *(float4*)&out[(size_t)gr * NC + c] = o;
        }
    }

    if (ATT) {
        __syncthreads();
        if (threadIdx.x == 0) {
            atomicMax(&g_mxu[slot * 2],     s_mx[0]);
            atomicMax(&g_mxu[slot * 2 + 1], s_mx[1]);
        }
    }
}

// ------------------------------ GAT aggregate -------------------------------
// Warp per dst node. Lane-parallel weight phase, broadcast gather phase with
// packed f32x2 accumulation (each lane owns 2 features -> 1 LDG.64 + 1 FMA2
// per edge). Global softmax shift (shift-invariant, bounded).
__global__ void k_agg(const float* __restrict__ h, const float* __restrict__ bias,
                      float* __restrict__ out, int relu, int slot) {
    int gw = (blockIdx.x * blockDim.x + threadIdx.x) >> 5;
    int lane = threadIdx.x & 31;
    if (gw >= NNODES) return;
    int beg = g_off[gw], end = g_off[gw + 1];
    float adv = g_ad[gw];
    float m = lrelu(fdec(g_mxu[slot * 2]) + fdec(g_mxu[slot * 2 + 1]));

    float wself = __expf(lrelu(g_as[gw] + adv) - m);
    float dsum = (lane == 0) ? wself : 0.f;

    unsigned long long acc;
    {
        unsigned long long hv = *(const unsigned long long*)&h[(size_t)gw * 64 + lane * 2];
        unsigned long long wd; DUP2(wd, wself);
        acc = 0ull;
        FMA2(acc, wd, hv);
    }

    for (int chunk = beg; chunk < end; chunk += 32) {
        int idx = chunk + lane;
        int s = 0; float w = 0.f;
        if (idx < end) {
            s = g_csr_src[idx];
            w = __expf(lrelu(g_as[s] + adv) - m);
        }
        dsum += w;
        int cnt = end - chunk;
        if (cnt >= 32) {
#pragma unroll 4
            for (int j = 0; j < 32; j++) {
                int   sj = __shfl_sync(0xffffffffu, s, j);
                float wj = __shfl_sync(0xffffffffu, w, j);
                unsigned long long hv = *(const unsigned long long*)&h[(size_t)sj * 64 + lane * 2];
                unsigned long long wd; DUP2(wd, wj);
                FMA2(acc, wd, hv);
            }
        } else {
            for (int j = 0; j < cnt; j++) {
                int   sj = __shfl_sync(0xffffffffu, s, j);
                float wj = __shfl_sync(0xffffffffu, w, j);
                unsigned long long hv = *(const unsigned long long*)&h[(size_t)sj * 64 + lane * 2];
                unsigned long long wd; DUP2(wd, wj);
                FMA2(acc, wd, hv);
            }
        }
    }
#pragma unroll
    for (int o = 16; o; o >>= 1) dsum += __shfl_xor_sync(0xffffffffu, dsum, o);

    float inv = 1.0f / (dsum + 1e-16f);
    float2 b = *(const float2*)&bias[lane * 2];
    float o0 = f2lo(acc) * inv + b.x;
    float o1 = f2hi(acc) * inv + b.y;
    if (relu) { o0 = fmaxf(o0, 0.f); o1 = fmaxf(o1, 0.f); }
    float2 ov = make_float2(o0, o1);
    *(float2*)&out[(size_t)gw * 64 + lane * 2] = ov;
}

// ------------------------------ launch --------------------------------------
extern "C" void kernel_launch(void* const* d_in, const int* in_sizes, int n_in,
                              void* d_out, int out_size) {
    const float* x    = (const float*)d_in[0];
    const void*  ei   = d_in[1];
    const float* W1   = (const float*)d_in[2];
    const float* b1   = (const float*)d_in[3];
    const float* Wc0  = (const float*)d_in[4];
    const float* as0  = (const float*)d_in[5];
    const float* ad0  = (const float*)d_in[6];
    const float* bi0  = (const float*)d_in[7];
    const float* Wc1  = (const float*)d_in[8];
    const float* as1  = (const float*)d_in[9];
    const float* ad1  = (const float*)d_in[10];
    const float* bi1  = (const float*)d_in[11];
    const float* W2   = (const float*)d_in[12];
    const float* b2   = (const float*)d_in[13];
    float*       outp = (float*)d_out;

    int E = in_sizes[1] / 2;
    if (E > EMAX) E = EMAX;

    float *pA = nullptr, *pB = nullptr;
    cudaGetSymbolAddress((void**)&pA, g_bufA);
    cudaGetSymbolAddress((void**)&pB, g_bufB);

    cudaFuncSetAttribute(k_gemm<FIN, HID, false, true, true, false>,
                         cudaFuncAttributeMaxDynamicSharedMemorySize, 2 * FIN * 64 * 4);

    const int NTILES = (NNODES + 63) / 64;

    // 0
    k_init<<<(NNODES + 255) / 256, 256>>>((const int*)ei, in_sizes[1]);
    // 1
    k_convert_hist<<<(E + 255) / 256, 256>>>(ei, E);
    // 2: h1 = relu(x @ W1 + b1)
    {
        size_t sm = (size_t)(2 * FIN * 64) * 4;
        k_gemm<FIN, HID, false, true, true, false><<<NTILES, 256, sm>>>(
            x, W1, b1, nullptr, nullptr, pA, -1);
    }
    // 3 (profiled): hc0 = h1 @ Wc0 ; attention dots + max
    {
        size_t sm = (size_t)(2 * HID * 64 + 128) * 4;
        k_gemm<HID, HID, true, false, false, false><<<NTILES, 256, sm>>>(
            pA, Wc0, nullptr, as0, ad0, pB, 0);
    }
    // 4, 5: CSR
    k_scan<<<(NNODES + 1023) / 1024, 1024>>>();
    k_scatter<<<(E + 255) / 256, 256>>>(E);
    // 6
    k_agg<<<(NNODES * 32 + 255) / 256, 256>>>(pB, bi0, pA, 1, 0);
    // 7: hc1 = g0 @ Wc1 ; attention dots + max
    {
        size_t sm = (size_t)(2 * HID * 64 + 128) * 4;
        k_gemm<HID, HID, true, false, false, false><<<NTILES, 256, sm>>>(
            pA, Wc1, nullptr, as1, ad1, pB, 1);
    }
    // 8
    k_agg<<<(NNODES * 32 + 255) / 256, 256>>>(pB, bi1, pA, 0, 1);
    // 9: logits + fused log_softmax
    {
        size_t sm = (size_t)(2 * HID * 64) * 4;
        k_gemm<HID, NCLS, false, true, false, true><<<NTILES, 256, sm>>>(
            pA, W2, b2, nullptr, nullptr, outp, -1);
    }
}

// round 7
// speedup vs baseline: 1.1958x; 1.0574x over previous
#include <cuda_runtime.h>
#include <cstdint>

#define NNODES 100000
#define EMAX   1700000
#define HID    64
#define FIN    128
#define NCLS   40

// ------------------------------ device scratch ------------------------------
__device__ float g_bufA[NNODES * HID];
__device__ float g_bufB[NNODES * HID];
__device__ float g_as[NNODES];
__device__ float g_ad[NNODES];
__device__ int   g_deg[NNODES];
__device__ int   g_off[NNODES + 1];
__device__ int   g_pos[NNODES];
__device__ int   g_csr_src[EMAX];
__device__ int   g_esrc[EMAX];
__device__ int   g_edst[EMAX];
__device__ int   g_bsum[128];
__device__ volatile int g_flag[128];
__device__ int   g_idx32;
__device__ unsigned g_mxu[4];

__device__ __forceinline__ float lrelu(float x) { return x > 0.f ? x : 0.2f * x; }

__device__ __forceinline__ unsigned fenc(float f) {
    unsigned u = __float_as_uint(f);
    return (u & 0x80000000u) ? ~u : (u | 0x80000000u);
}
__device__ __forceinline__ float fdec(unsigned k) {
    return (k & 0x80000000u) ? __uint_as_float(k & 0x7fffffffu)
                             : __uint_as_float(~k);
}

#define FMA2(d, a, b) asm("fma.rn.f32x2 %0, %1, %2, %0;" : "+l"(d) : "l"(a), "l"(b))
#define DUP2(d, f)    asm("mov.b64 %0, {%1, %1};" : "=l"(d) : "f"(f))

__device__ __forceinline__ float f2lo(unsigned long long v) {
    return __uint_as_float((unsigned)(v & 0xffffffffu));
}
__device__ __forceinline__ float f2hi(unsigned long long v) {
    return __uint_as_float((unsigned)(v >> 32));
}

// --------------------- init: zero deg/flags/maxima, detect dtype ------------
__global__ void k_init(const int* __restrict__ w, int nwords) {
    __shared__ int nz;
    int i = blockIdx.x * blockDim.x + threadIdx.x;
    if (i < NNODES) g_deg[i] = 0;
    if (i < 4) g_mxu[i] = 0u;
    if (i < 128) g_flag[i] = 0;
    if (blockIdx.x == 0) {
        if (threadIdx.x == 0) nz = 0;
        __syncthreads();
        int n = nwords < 4096 ? nwords : 4096;
        int found = 0;
        for (int j = 2 * threadIdx.x + 1; j < n; j += 2 * blockDim.x)
            if (w[j] != 0) found = 1;
        if (found) atomicExch(&nz, 1);
        __syncthreads();
        if (threadIdx.x == 0) g_idx32 = nz;
    }
}

__global__ void k_convert_hist(const void* __restrict__ ei, int E) {
    int e = blockIdx.x * blockDim.x + threadIdx.x;
    if (e >= E) return;
    int s, d;
    if (g_idx32) {
        const int* p = (const int*)ei;
        s = p[e]; d = p[E + e];
    } else {
        const long long* p = (const long long*)ei;
        s = (int)p[e]; d = (int)p[E + e];
    }
    g_esrc[e] = s;
    g_edst[e] = d;
    atomicAdd(&g_deg[d], 1);
}

// ---------------- single-kernel scan (all 98 blocks resident) ---------------
__global__ void k_scan() {
    __shared__ int sh[1024];
    __shared__ int s_off;
    int bid = blockIdx.x;
    int tid = threadIdx.x;
    int i = bid * 1024 + tid;
    int v = (i < NNODES) ? g_deg[i] : 0;
    sh[tid] = v;
    if (tid == 0) s_off = 0;
    __syncthreads();
    for (int o = 1; o < 1024; o <<= 1) {
        int t = 0;
        if (tid >= o) t = sh[tid - o];
        __syncthreads();
        sh[tid] += t;
        __syncthreads();
    }
    if (tid == 1023) {
        g_bsum[bid] = sh[1023];
        __threadfence();
        g_flag[bid] = 1;
    }
    if (tid < bid) {
        while (g_flag[tid] == 0) { }
        atomicAdd(&s_off, g_bsum[tid]);
    }
    __syncthreads();
    if (i < NNODES) {
        int incl = sh[tid] + s_off;
        int excl = incl - v;
        g_off[i] = excl;
        g_pos[i] = excl;
        if (i == NNODES - 1) g_off[NNODES] = incl;
    }
}

__global__ void k_scatter(int E) {
    int e = blockIdx.x * blockDim.x + threadIdx.x;
    if (e < E) {
        int d = g_edst[e];
        int p = atomicAdd(&g_pos[d], 1);
        g_csr_src[p] = g_esrc[e];
    }
}

// ------------------------------ GEMM (FFMA2, 8x8) ---------------------------
// 128-thread CTA, 128-row tile, 8 rows x 8 cols per thread.
// sXT: transposed X tile [K][128] with XOR-4 swizzle keyed on (k>>2)&7
// (store <=2-way conflicted; LDS.128 loads conflict-free, row order preserved
// because (4+i)^4 = i for i<4). sW: [K][64], cols zero-padded.
template <int K, int NC, bool ATT, bool BIAS, bool RELU, bool LSM>
__global__ void k_gemm(const float* __restrict__ X, const float* __restrict__ Wg,
                       const float* __restrict__ bias,
                       const float* __restrict__ attS, const float* __restrict__ attD,
                       float* __restrict__ out, int slot) {
    extern __shared__ float smem[];
    float* sW  = smem;               // [K][64]
    float* sXT = smem + K * 64;      // [K][128] swizzled
    float* sAS = sXT + K * 128;      // [64] if ATT
    float* sAD = sAS + 64;
    __shared__ unsigned s_mx[2];

    for (int i = threadIdx.x; i < K * 64; i += 128) sW[i] = 0.f;
    if (ATT) {
        if (threadIdx.x < 2) s_mx[threadIdx.x] = 0u;
        for (int i = threadIdx.x; i < 64; i += 128) {
            sAS[i] = (i < NC) ? attS[i] : 0.f;
            sAD[i] = (i < NC) ? attD[i] : 0.f;
        }
    }
    __syncthreads();
    for (int i = threadIdx.x; i < K * NC; i += 128)
        sW[(i / NC) * 64 + (i % NC)] = Wg[i];

    const int base = blockIdx.x * 128;
    constexpr int K4 = K / 4;
    // transposed+swizzled store of the X tile (gmem coalesced)
    for (int u = threadIdx.x; u < 128 * K4; u += 128) {
        int kq  = u & (K4 - 1);
        int row = u / K4;
        int gr = base + row;
        float4 v = make_float4(0.f, 0.f, 0.f, 0.f);
        if (gr < NNODES) v = *(const float4*)&X[(size_t)gr * K + kq * 4];
        int rsw = row ^ ((kq & 7) * 4);
        sXT[(kq * 4 + 0) * 128 + rsw] = v.x;
        sXT[(kq * 4 + 1) * 128 + rsw] = v.y;
        sXT[(kq * 4 + 2) * 128 + rsw] = v.z;
        sXT[(kq * 4 + 3) * 128 + rsw] = v.w;
    }
    __syncthreads();

    const int cg = threadIdx.x & 7;     // 8 cols: cg*8 .. +7
    const int rg = threadIdx.x >> 3;    // 8 rows: rg*8 .. +7

    unsigned long long acc[8][4];
#pragma unroll
    for (int r = 0; r < 8; r++)
#pragma unroll
        for (int cp = 0; cp < 4; cp++) acc[r][cp] = 0ull;

#pragma unroll 4
    for (int k = 0; k < K; k++) {
        int s4 = ((k >> 2) & 7) * 4;
        int a0 = (rg * 8) ^ s4;
        float4 xa = *(const float4*)&sXT[k * 128 + a0];        // rows rg*8..+3
        float4 xb = *(const float4*)&sXT[k * 128 + (a0 ^ 4)];  // rows rg*8+4..+7
        double2 wva = *(const double2*)&sW[k * 64 + cg * 8];
        double2 wvb = *(const double2*)&sW[k * 64 + cg * 8 + 4];
        unsigned long long w01 = __double_as_longlong(wva.x);
        unsigned long long w23 = __double_as_longlong(wva.y);
        unsigned long long w45 = __double_as_longlong(wvb.x);
        unsigned long long w67 = __double_as_longlong(wvb.y);
        unsigned long long xd;
        DUP2(xd, xa.x);
        FMA2(acc[0][0], xd, w01); FMA2(acc[0][1], xd, w23);
        FMA2(acc[0][2], xd, w45); FMA2(acc[0][3], xd, w67);
        DUP2(xd, xa.y);
        FMA2(acc[1][0], xd, w01); FMA2(acc[1][1], xd, w23);
        FMA2(acc[1][2], xd, w45); FMA2(acc[1][3], xd, w67);
        DUP2(xd, xa.z);
        FMA2(acc[2][0], xd, w01); FMA2(acc[2][1], xd, w23);
        FMA2(acc[2][2], xd, w45); FMA2(acc[2][3], xd, w67);
        DUP2(xd, xa.w);
        FMA2(acc[3][0], xd, w01); FMA2(acc[3][1], xd, w23);
        FMA2(acc[3][2], xd, w45); FMA2(acc[3][3], xd, w67);
        DUP2(xd, xb.x);
        FMA2(acc[4][0], xd, w01); FMA2(acc[4][1], xd, w23);
        FMA2(acc[4][2], xd, w45); FMA2(acc[4][3], xd, w67);
        DUP2(xd, xb.y);
        FMA2(acc[5][0], xd, w01); FMA2(acc[5][1], xd, w23);
        FMA2(acc[5][2], xd, w45); FMA2(acc[5][3], xd, w67);
        DUP2(xd, xb.z);
        FMA2(acc[6][0], xd, w01); FMA2(acc[6][1], xd, w23);
        FMA2(acc[6][2], xd, w45); FMA2(acc[6][3], xd, w67);
        DUP2(xd, xb.w);
        FMA2(acc[7][0], xd, w01); FMA2(acc[7][1], xd, w23);
        FMA2(acc[7][2], xd, w45); FMA2(acc[7][3], xd, w67);
    }

    const int c0 = cg * 8;
    float4 ba = make_float4(0.f, 0.f, 0.f, 0.f), bb = ba;
    if (BIAS && c0 < NC) {
        ba = *(const float4*)&bias[c0];
        bb = *(const float4*)&bias[c0 + 4];
    }
    float4 sa1, sa2, sd1, sd2;
    if (ATT) {
        sa1 = *(const float4*)&sAS[c0]; sa2 = *(const float4*)&sAS[c0 + 4];
        sd1 = *(const float4*)&sAD[c0]; sd2 = *(const float4*)&sAD[c0 + 4];
    }

#pragma unroll
    for (int r = 0; r < 8; r++) {
        int gr = base + rg * 8 + r;
        float4 oa, ob;
        oa.x = f2lo(acc[r][0]); oa.y = f2hi(acc[r][0]);
        oa.z = f2lo(acc[r][1]); oa.w = f2hi(acc[r][1]);
        ob.x = f2lo(acc[r][2]); ob.y = f2hi(acc[r][2]);
        ob.z = f2lo(acc[r][3]); ob.w = f2hi(acc[r][3]);

        if (ATT) {
            float ps = oa.x * sa1.x + oa.y * sa1.y + oa.z * sa1.z + oa.w * sa1.w
                     + ob.x * sa2.x + ob.y * sa2.y + ob.z * sa2.z + ob.w * sa2.w;
            float pd = oa.x * sd1.x + oa.y * sd1.y + oa.z * sd1.z + oa.w * sd1.w
                     + ob.x * sd2.x + ob.y * sd2.y + ob.z * sd2.z + ob.w * sd2.w;
#pragma unroll
            for (int off = 4; off; off >>= 1) {
                ps += __shfl_xor_sync(0xffffffffu, ps, off, 8);
                pd += __shfl_xor_sync(0xffffffffu, pd, off, 8);
            }
            if (cg == 0 && gr < NNODES) {
                g_as[gr] = ps; g_ad[gr] = pd;
                atomicMax(&s_mx[0], fenc(ps));
                atomicMax(&s_mx[1], fenc(pd));
            }
        }

        if (BIAS && c0 < NC) {
            oa.x += ba.x; oa.y += ba.y; oa.z += ba.z; oa.w += ba.w;
            ob.x += bb.x; ob.y += bb.y; ob.z += bb.z; ob.w += bb.w;
        }

        if (LSM) {
            float lm = -1e30f;
            if (c0 < NC) {
                lm = fmaxf(fmaxf(fmaxf(oa.x, oa.y), fmaxf(oa.z, oa.w)),
                           fmaxf(fmaxf(ob.x, ob.y), fmaxf(ob.z, ob.w)));
            }
#pragma unroll
            for (int off = 4; off; off >>= 1)
                lm = fmaxf(lm, __shfl_xor_sync(0xffffffffu, lm, off, 8));
            float le = 0.f;
            if (c0 < NC) {
                le = __expf(oa.x - lm) + __expf(oa.y - lm) + __expf(oa.z - lm) + __expf(oa.w - lm)
                   + __expf(ob.x - lm) + __expf(ob.y - lm) + __expf(ob.z - lm) + __expf(ob.w - lm);
            }
#pragma unroll
            for (int off = 4; off; off >>= 1)
                le += __shfl_xor_sync(0xffffffffu, le, off, 8);
            float lse = lm + __logf(le);
            if (c0 < NC && gr < NNODES) {
                oa.x -= lse; oa.y -= lse; oa.z -= lse; oa.w -= lse;
                ob.x -= lse; ob.y -= lse; ob.z -= lse; ob.w -= lse;
                *(float4*)&out[(size_t)gr * NC + c0] = oa;
                *(float4*)&out[(size_t)gr * NC + c0 + 4] = ob;
            }
        } else if (c0 < NC && gr < NNODES) {
            if (RELU) {
                oa.x = fmaxf(oa.x, 0.f); oa.y = fmaxf(oa.y, 0.f);
                oa.z = fmaxf(oa.z, 0.f); oa.w = fmaxf(oa.w, 0.f);
                ob.x = fmaxf(ob.x, 0.f); ob.y = fmaxf(ob.y, 0.f);
                ob.z = fmaxf(ob.z, 0.f); ob.w = fmaxf(ob.w, 0.f);
            }
            *(float4*)&out[(size_t)gr * NC + c0] = oa;
            *(float4*)&out[(size_t)gr * NC + c0 + 4] = ob;
        }
    }

    if (ATT) {
        __syncthreads();
        if (threadIdx.x == 0) {
            atomicMax(&g_mxu[slot * 2],     s_mx[0]);
            atomicMax(&g_mxu[slot * 2 + 1], s_mx[1]);
        }
    }
}

// ------------------------------ GAT aggregate -------------------------------
__global__ void k_agg(const float* __restrict__ h, const float* __restrict__ bias,
                      float* __restrict__ out, int relu, int slot) {
    int gw = (blockIdx.x * blockDim.x + threadIdx.x) >> 5;
    int lane = threadIdx.x & 31;
    if (gw >= NNODES) return;
    int beg = g_off[gw], end = g_off[gw + 1];
    float adv = g_ad[gw];
    float m = lrelu(fdec(g_mxu[slot * 2]) + fdec(g_mxu[slot * 2 + 1]));

    float wself = __expf(lrelu(g_as[gw] + adv) - m);
    float dsum = (lane == 0) ? wself : 0.f;

    unsigned long long acc;
    {
        unsigned long long hv = *(const unsigned long long*)&h[(size_t)gw * 64 + lane * 2];
        unsigned long long wd; DUP2(wd, wself);
        acc = 0ull;
        FMA2(acc, wd, hv);
    }

    for (int chunk = beg; chunk < end; chunk += 32) {
        int idx = chunk + lane;
        int s = 0; float w = 0.f;
        if (idx < end) {
            s = g_csr_src[idx];
            w = __expf(lrelu(g_as[s] + adv) - m);
        }
        dsum += w;
        int cnt = end - chunk;
        if (cnt >= 32) {
#pragma unroll 4
            for (int j = 0; j < 32; j++) {
                int   sj = __shfl_sync(0xffffffffu, s, j);
                float wj = __shfl_sync(0xffffffffu, w, j);
                unsigned long long hv = *(const unsigned long long*)&h[(size_t)sj * 64 + lane * 2];
                unsigned long long wd; DUP2(wd, wj);
                FMA2(acc, wd, hv);
            }
        } else {
            for (int j = 0; j < cnt; j++) {
                int   sj = __shfl_sync(0xffffffffu, s, j);
                float wj = __shfl_sync(0xffffffffu, w, j);
                unsigned long long hv = *(const unsigned long long*)&h[(size_t)sj * 64 + lane * 2];
                unsigned long long wd; DUP2(wd, wj);
                FMA2(acc, wd, hv);
            }
        }
    }
#pragma unroll
    for (int o = 16; o; o >>= 1) dsum += __shfl_xor_sync(0xffffffffu, dsum, o);

    float inv = 1.0f / (dsum + 1e-16f);
    float2 b = *(const float2*)&bias[lane * 2];
    float o0 = f2lo(acc) * inv + b.x;
    float o1 = f2hi(acc) * inv + b.y;
    if (relu) { o0 = fmaxf(o0, 0.f); o1 = fmaxf(o1, 0.f); }
    float2 ov = make_float2(o0, o1);
    *(float2*)&out[(size_t)gw * 64 + lane * 2] = ov;
}

// ------------------------------ launch --------------------------------------
extern "C" void kernel_launch(void* const* d_in, const int* in_sizes, int n_in,
                              void* d_out, int out_size) {
    const float* x    = (const float*)d_in[0];
    const void*  ei   = d_in[1];
    const float* W1   = (const float*)d_in[2];
    const float* b1   = (const float*)d_in[3];
    const float* Wc0  = (const float*)d_in[4];
    const float* as0  = (const float*)d_in[5];
    const float* ad0  = (const float*)d_in[6];
    const float* bi0  = (const float*)d_in[7];
    const float* Wc1  = (const float*)d_in[8];
    const float* as1  = (const float*)d_in[9];
    const float* ad1  = (const float*)d_in[10];
    const float* bi1  = (const float*)d_in[11];
    const float* W2   = (const float*)d_in[12];
    const float* b2   = (const float*)d_in[13];
    float*       outp = (float*)d_out;

    int E = in_sizes[1] / 2;
    if (E > EMAX) E = EMAX;

    float *pA = nullptr, *pB = nullptr;
    cudaGetSymbolAddress((void**)&pA, g_bufA);
    cudaGetSymbolAddress((void**)&pB, g_bufB);

    size_t sm1 = (size_t)(FIN * 64 + FIN * 128) * 4;            // 98304
    size_t smA = (size_t)(HID * 64 + HID * 128 + 128) * 4;      // 49664
    size_t sm4 = (size_t)(HID * 64 + HID * 128) * 4;            // 49152
    cudaFuncSetAttribute(k_gemm<FIN, HID, false, true, true, false>,
                         cudaFuncAttributeMaxDynamicSharedMemorySize, (int)sm1);
    cudaFuncSetAttribute(k_gemm<HID, HID, true, false, false, false>,
                         cudaFuncAttributeMaxDynamicSharedMemorySize, (int)smA);
    cudaFuncSetAttribute(k_gemm<HID, NCLS, false, true, false, true>,
                         cudaFuncAttributeMaxDynamicSharedMemorySize, (int)sm4);

    const int NTILES = (NNODES + 127) / 128;

    // 0
    k_init<<<(NNODES + 255) / 256, 256>>>((const int*)ei, in_sizes[1]);
    // 1
    k_convert_hist<<<(E + 255) / 256, 256>>>(ei, E);
    // 2: h1 = relu(x @ W1 + b1)
    k_gemm<FIN, HID, false, true, true, false><<<NTILES, 128, sm1>>>(
        x, W1, b1, nullptr, nullptr, pA, -1);
    // 3 (profiled): hc0 = h1 @ Wc0 ; attention dots + max
    k_gemm<HID, HID, true, false, false, false><<<NTILES, 128, smA>>>(
        pA, Wc0, nullptr, as0, ad0, pB, 0);
    // 4, 5: CSR
    k_scan<<<(NNODES + 1023) / 1024, 1024>>>();
    k_scatter<<<(E + 255) / 256, 256>>>(E);
    // 6
    k_agg<<<(NNODES * 32 + 255) / 256, 256>>>(pB, bi0, pA, 1, 0);
    // 7: hc1 = g0 @ Wc1 ; attention dots + max
    k_gemm<HID, HID, true, false, false, false><<<NTILES, 128, smA>>>(
        pA, Wc1, nullptr, as1, ad1, pB, 1);
    // 8
    k_agg<<<(NNODES * 32 + 255) / 256, 256>>>(pB, bi1, pA, 0, 1);
    // 9: logits + fused log_softmax
    k_gemm<HID, NCLS, false, true, false, true><<<NTILES, 128, sm4>>>(
        pA, W2, b2, nullptr, nullptr, outp, -1);
}

// round 8
// speedup vs baseline: 1.2757x; 1.0668x over previous
#include <cuda_runtime.h>
#include <cstdint>

#define NNODES 100000
#define EMAX   1700000
#define HID    64
#define FIN    128
#define NCLS   40

// ------------------------------ device scratch ------------------------------
__device__ float g_bufA[NNODES * HID];
__device__ float g_bufB[NNODES * HID];
__device__ float g_as[NNODES];
__device__ float g_ad[NNODES];
__device__ int   g_deg[NNODES];
__device__ int   g_off[NNODES + 1];
__device__ int   g_pos[NNODES];
__device__ int   g_csr_src[EMAX];
__device__ int   g_esrc[EMAX];
__device__ int   g_edst[EMAX];
__device__ int   g_bsum[128];
__device__ volatile int g_flag[128];
__device__ int   g_idx32;
__device__ unsigned g_mxu[4];

__device__ __forceinline__ float lrelu(float x) { return x > 0.f ? x : 0.2f * x; }

__device__ __forceinline__ unsigned fenc(float f) {
    unsigned u = __float_as_uint(f);
    return (u & 0x80000000u) ? ~u : (u | 0x80000000u);
}
__device__ __forceinline__ float fdec(unsigned k) {
    return (k & 0x80000000u) ? __uint_as_float(k & 0x7fffffffu)
                             : __uint_as_float(~k);
}

#define FMA2(d, a, b) asm("fma.rn.f32x2 %0, %1, %2, %0;" : "+l"(d) : "l"(a), "l"(b))
#define DUP2(d, f)    asm("mov.b64 %0, {%1, %1};" : "=l"(d) : "f"(f))

__device__ __forceinline__ float f2lo(unsigned long long v) {
    return __uint_as_float((unsigned)(v & 0xffffffffu));
}
__device__ __forceinline__ float f2hi(unsigned long long v) {
    return __uint_as_float((unsigned)(v >> 32));
}

// --------------------- init: zero deg/flags/maxima, detect dtype ------------
__global__ void k_init(const int* __restrict__ w, int nwords) {
    __shared__ int nz;
    int i = blockIdx.x * blockDim.x + threadIdx.x;
    if (i < NNODES) g_deg[i] = 0;
    if (i < 4) g_mxu[i] = 0u;
    if (i < 128) g_flag[i] = 0;
    if (blockIdx.x == 0) {
        if (threadIdx.x == 0) nz = 0;
        __syncthreads();
        int n = nwords < 4096 ? nwords : 4096;
        int found = 0;
        for (int j = 2 * threadIdx.x + 1; j < n; j += 2 * blockDim.x)
            if (w[j] != 0) found = 1;
        if (found) atomicExch(&nz, 1);
        __syncthreads();
        if (threadIdx.x == 0) g_idx32 = nz;
    }
}

__global__ void k_convert_hist(const void* __restrict__ ei, int E) {
    int e = blockIdx.x * blockDim.x + threadIdx.x;
    if (e >= E) return;
    int s, d;
    if (g_idx32) {
        const int* p = (const int*)ei;
        s = p[e]; d = p[E + e];
    } else {
        const long long* p = (const long long*)ei;
        s = (int)p[e]; d = (int)p[E + e];
    }
    g_esrc[e] = s;
    g_edst[e] = d;
    atomicAdd(&g_deg[d], 1);
}

// ---------------- single-kernel scan (all 98 blocks resident) ---------------
__global__ void k_scan() {
    __shared__ int sh[1024];
    __shared__ int s_off;
    int bid = blockIdx.x;
    int tid = threadIdx.x;
    int i = bid * 1024 + tid;
    int v = (i < NNODES) ? g_deg[i] : 0;
    sh[tid] = v;
    if (tid == 0) s_off = 0;
    __syncthreads();
    for (int o = 1; o < 1024; o <<= 1) {
        int t = 0;
        if (tid >= o) t = sh[tid - o];
        __syncthreads();
        sh[tid] += t;
        __syncthreads();
    }
    if (tid == 1023) {
        g_bsum[bid] = sh[1023];
        __threadfence();
        g_flag[bid] = 1;
    }
    if (tid < bid) {
        while (g_flag[tid] == 0) { }
        atomicAdd(&s_off, g_bsum[tid]);
    }
    __syncthreads();
    if (i < NNODES) {
        int incl = sh[tid] + s_off;
        int excl = incl - v;
        g_off[i] = excl;
        g_pos[i] = excl;
        if (i == NNODES - 1) g_off[NNODES] = incl;
    }
}

__global__ void k_scatter(int E) {
    int e = blockIdx.x * blockDim.x + threadIdx.x;
    if (e < E) {
        int d = g_edst[e];
        int p = atomicAdd(&g_pos[d], 1);
        g_csr_src[p] = g_esrc[e];
    }
}

// ------------------------------ GEMM (FFMA2, 8x8) ---------------------------
template <int K, int NC, bool ATT, bool BIAS, bool RELU, bool LSM>
__global__ void k_gemm(const float* __restrict__ X, const float* __restrict__ Wg,
                       const float* __restrict__ bias,
                       const float* __restrict__ attS, const float* __restrict__ attD,
                       float* __restrict__ out, int slot) {
    extern __shared__ float smem[];
    float* sW  = smem;               // [K][64]
    float* sXT = smem + K * 64;      // [K][128] swizzled
    float* sAS = sXT + K * 128;      // [64] if ATT
    float* sAD = sAS + 64;
    __shared__ unsigned s_mx[2];

    if (NC != 64) {
        for (int i = threadIdx.x; i < K * 64; i += 128) sW[i] = 0.f;
    }
    if (ATT) {
        if (threadIdx.x < 2) s_mx[threadIdx.x] = 0u;
        for (int i = threadIdx.x; i < 64; i += 128) {
            sAS[i] = (i < NC) ? attS[i] : 0.f;
            sAD[i] = (i < NC) ? attD[i] : 0.f;
        }
    }
    if (NC != 64) __syncthreads();
    for (int i = threadIdx.x; i < K * NC; i += 128)
        sW[(i / NC) * 64 + (i % NC)] = Wg[i];

    const int base = blockIdx.x * 128;
    constexpr int K4 = K / 4;
    for (int u = threadIdx.x; u < 128 * K4; u += 128) {
        int kq  = u & (K4 - 1);
        int row = u / K4;
        int gr = base + row;
        float4 v = make_float4(0.f, 0.f, 0.f, 0.f);
        if (gr < NNODES) v = *(const float4*)&X[(size_t)gr * K + kq * 4];
        int rsw = row ^ ((kq & 7) * 4);
        sXT[(kq * 4 + 0) * 128 + rsw] = v.x;
        sXT[(kq * 4 + 1) * 128 + rsw] = v.y;
        sXT[(kq * 4 + 2) * 128 + rsw] = v.z;
        sXT[(kq * 4 + 3) * 128 + rsw] = v.w;
    }
    __syncthreads();

    const int cg = threadIdx.x & 7;     // 8 cols: cg*8 .. +7
    const int rg = threadIdx.x >> 3;    // 8 rows: rg*8 .. +7

    unsigned long long acc[8][4];
#pragma unroll
    for (int r = 0; r < 8; r++)
#pragma unroll
        for (int cp = 0; cp < 4; cp++) acc[r][cp] = 0ull;

#pragma unroll 4
    for (int k = 0; k < K; k++) {
        int s4 = ((k >> 2) & 7) * 4;
        int a0 = (rg * 8) ^ s4;
        float4 xa = *(const float4*)&sXT[k * 128 + a0];
        float4 xb = *(const float4*)&sXT[k * 128 + (a0 ^ 4)];
        double2 wva = *(const double2*)&sW[k * 64 + cg * 8];
        double2 wvb = *(const double2*)&sW[k * 64 + cg * 8 + 4];
        unsigned long long w01 = __double_as_longlong(wva.x);
        unsigned long long w23 = __double_as_longlong(wva.y);
        unsigned long long w45 = __double_as_longlong(wvb.x);
        unsigned long long w67 = __double_as_longlong(wvb.y);
        unsigned long long xd;
        DUP2(xd, xa.x);
        FMA2(acc[0][0], xd, w01); FMA2(acc[0][1], xd, w23);
        FMA2(acc[0][2], xd, w45); FMA2(acc[0][3], xd, w67);
        DUP2(xd, xa.y);
        FMA2(acc[1][0], xd, w01); FMA2(acc[1][1], xd, w23);
        FMA2(acc[1][2], xd, w45); FMA2(acc[1][3], xd, w67);
        DUP2(xd, xa.z);
        FMA2(acc[2][0], xd, w01); FMA2(acc[2][1], xd, w23);
        FMA2(acc[2][2], xd, w45); FMA2(acc[2][3], xd, w67);
        DUP2(xd, xa.w);
        FMA2(acc[3][0], xd, w01); FMA2(acc[3][1], xd, w23);
        FMA2(acc[3][2], xd, w45); FMA2(acc[3][3], xd, w67);
        DUP2(xd, xb.x);
        FMA2(acc[4][0], xd, w01); FMA2(acc[4][1], xd, w23);
        FMA2(acc[4][2], xd, w45); FMA2(acc[4][3], xd, w67);
        DUP2(xd, xb.y);
        FMA2(acc[5][0], xd, w01); FMA2(acc[5][1], xd, w23);
        FMA2(acc[5][2], xd, w45); FMA2(acc[5][3], xd, w67);
        DUP2(xd, xb.z);
        FMA2(acc[6][0], xd, w01); FMA2(acc[6][1], xd, w23);
        FMA2(acc[6][2], xd, w45); FMA2(acc[6][3], xd, w67);
        DUP2(xd, xb.w);
        FMA2(acc[7][0], xd, w01); FMA2(acc[7][1], xd, w23);
        FMA2(acc[7][2], xd, w45); FMA2(acc[7][3], xd, w67);
    }

    const int c0 = cg * 8;
    float4 ba = make_float4(0.f, 0.f, 0.f, 0.f), bb = ba;
    if (BIAS && c0 < NC) {
        ba = *(const float4*)&bias[c0];
        bb = *(const float4*)&bias[c0 + 4];
    }
    float4 sa1, sa2, sd1, sd2;
    if (ATT) {
        sa1 = *(const float4*)&sAS[c0]; sa2 = *(const float4*)&sAS[c0 + 4];
        sd1 = *(const float4*)&sAD[c0]; sd2 = *(const float4*)&sAD[c0 + 4];
    }

#pragma unroll
    for (int r = 0; r < 8; r++) {
        int gr = base + rg * 8 + r;
        float4 oa, ob;
        oa.x = f2lo(acc[r][0]); oa.y = f2hi(acc[r][0]);
        oa.z = f2lo(acc[r][1]); oa.w = f2hi(acc[r][1]);
        ob.x = f2lo(acc[r][2]); ob.y = f2hi(acc[r][2]);
        ob.z = f2lo(acc[r][3]); ob.w = f2hi(acc[r][3]);

        if (ATT) {
            float ps = oa.x * sa1.x + oa.y * sa1.y + oa.z * sa1.z + oa.w * sa1.w
                     + ob.x * sa2.x + ob.y * sa2.y + ob.z * sa2.z + ob.w * sa2.w;
            float pd = oa.x * sd1.x + oa.y * sd1.y + oa.z * sd1.z + oa.w * sd1.w
                     + ob.x * sd2.x + ob.y * sd2.y + ob.z * sd2.z + ob.w * sd2.w;
#pragma unroll
            for (int off = 4; off; off >>= 1) {
                ps += __shfl_xor_sync(0xffffffffu, ps, off, 8);
                pd += __shfl_xor_sync(0xffffffffu, pd, off, 8);
            }
            if (cg == 0 && gr < NNODES) {
                g_as[gr] = ps; g_ad[gr] = pd;
                atomicMax(&s_mx[0], fenc(ps));
                atomicMax(&s_mx[1], fenc(pd));
            }
        }

        if (BIAS && c0 < NC) {
            oa.x += ba.x; oa.y += ba.y; oa.z += ba.z; oa.w += ba.w;
            ob.x += bb.x; ob.y += bb.y; ob.z += bb.z; ob.w += bb.w;
        }

        if (LSM) {
            float lm = -1e30f;
            if (c0 < NC) {
                lm = fmaxf(fmaxf(fmaxf(oa.x, oa.y), fmaxf(oa.z, oa.w)),
                           fmaxf(fmaxf(ob.x, ob.y), fmaxf(ob.z, ob.w)));
            }
#pragma unroll
            for (int off = 4; off; off >>= 1)
                lm = fmaxf(lm, __shfl_xor_sync(0xffffffffu, lm, off, 8));
            float le = 0.f;
            if (c0 < NC) {
                le = __expf(oa.x - lm) + __expf(oa.y - lm) + __expf(oa.z - lm) + __expf(oa.w - lm)
                   + __expf(ob.x - lm) + __expf(ob.y - lm) + __expf(ob.z - lm) + __expf(ob.w - lm);
            }
#pragma unroll
            for (int off = 4; off; off >>= 1)
                le += __shfl_xor_sync(0xffffffffu, le, off, 8);
            float lse = lm + __logf(le);
            if (c0 < NC && gr < NNODES) {
                oa.x -= lse; oa.y -= lse; oa.z -= lse; oa.w -= lse;
                ob.x -= lse; ob.y -= lse; ob.z -= lse; ob.w -= lse;
                *(float4*)&out[(size_t)gr * NC + c0] = oa;
                *(float4*)&out[(size_t)gr * NC + c0 + 4] = ob;
            }
        } else if (c0 < NC && gr < NNODES) {
            if (RELU) {
                oa.x = fmaxf(oa.x, 0.f); oa.y = fmaxf(oa.y, 0.f);
                oa.z = fmaxf(oa.z, 0.f); oa.w = fmaxf(oa.w, 0.f);
                ob.x = fmaxf(ob.x, 0.f); ob.y = fmaxf(ob.y, 0.f);
                ob.z = fmaxf(ob.z, 0.f); ob.w = fmaxf(ob.w, 0.f);
            }
            *(float4*)&out[(size_t)gr * NC + c0] = oa;
            *(float4*)&out[(size_t)gr * NC + c0 + 4] = ob;
        }
    }

    if (ATT) {
        __syncthreads();
        if (threadIdx.x == 0) {
            atomicMax(&g_mxu[slot * 2],     s_mx[0]);
            atomicMax(&g_mxu[slot * 2 + 1], s_mx[1]);
        }
    }
}

// ------------------------------ GAT aggregate -------------------------------
__global__ void k_agg(const float* __restrict__ h, const float* __restrict__ bias,
                      float* __restrict__ out, int relu, int slot) {
    int gw = (blockIdx.x * blockDim.x + threadIdx.x) >> 5;
    int lane = threadIdx.x & 31;
    if (gw >= NNODES) return;
    int beg = g_off[gw], end = g_off[gw + 1];
    float adv = g_ad[gw];
    float m = lrelu(fdec(g_mxu[slot * 2]) + fdec(g_mxu[slot * 2 + 1]));

    float wself = __expf(lrelu(g_as[gw] + adv) - m);
    float dsum = (lane == 0) ? wself : 0.f;

    unsigned long long acc;
    {
        unsigned long long hv = *(const unsigned long long*)&h[(size_t)gw * 64 + lane * 2];
        unsigned long long wd; DUP2(wd, wself);
        acc = 0ull;
        FMA2(acc, wd, hv);
    }

    for (int chunk = beg; chunk < end; chunk += 32) {
        int idx = chunk + lane;
        int s = 0; float w = 0.f;
        if (idx < end) {
            s = g_csr_src[idx];
            w = __expf(lrelu(g_as[s] + adv) - m);
        }
        dsum += w;
        int cnt = end - chunk;
        if (cnt >= 32) {
#pragma unroll 4
            for (int j = 0; j < 32; j++) {
                int   sj = __shfl_sync(0xffffffffu, s, j);
                float wj = __shfl_sync(0xffffffffu, w, j);
                unsigned long long hv = *(const unsigned long long*)&h[(size_t)sj * 64 + lane * 2];
                unsigned long long wd; DUP2(wd, wj);
                FMA2(acc, wd, hv);
            }
        } else {
            for (int j = 0; j < cnt; j++) {
                int   sj = __shfl_sync(0xffffffffu, s, j);
                float wj = __shfl_sync(0xffffffffu, w, j);
                unsigned long long hv = *(const unsigned long long*)&h[(size_t)sj * 64 + lane * 2];
                unsigned long long wd; DUP2(wd, wj);
                FMA2(acc, wd, hv);
            }
        }
    }
#pragma unroll
    for (int o = 16; o; o >>= 1) dsum += __shfl_xor_sync(0xffffffffu, dsum, o);

    float inv = 1.0f / (dsum + 1e-16f);
    float2 b = *(const float2*)&bias[lane * 2];
    float o0 = f2lo(acc) * inv + b.x;
    float o1 = f2hi(acc) * inv + b.y;
    if (relu) { o0 = fmaxf(o0, 0.f); o1 = fmaxf(o1, 0.f); }
    float2 ov = make_float2(o0, o1);
    *(float2*)&out[(size_t)gw * 64 + lane * 2] = ov;
}

// ------------------------------ launch --------------------------------------
extern "C" void kernel_launch(void* const* d_in, const int* in_sizes, int n_in,
                              void* d_out, int out_size) {
    const float* x    = (const float*)d_in[0];
    const void*  ei   = d_in[1];
    const float* W1   = (const float*)d_in[2];
    const float* b1   = (const float*)d_in[3];
    const float* Wc0  = (const float*)d_in[4];
    const float* as0  = (const float*)d_in[5];
    const float* ad0  = (const float*)d_in[6];
    const float* bi0  = (const float*)d_in[7];
    const float* Wc1  = (const float*)d_in[8];
    const float* as1  = (const float*)d_in[9];
    const float* ad1  = (const float*)d_in[10];
    const float* bi1  = (const float*)d_in[11];
    const float* W2   = (const float*)d_in[12];
    const float* b2   = (const float*)d_in[13];
    float*       outp = (float*)d_out;

    int E = in_sizes[1] / 2;
    if (E > EMAX) E = EMAX;

    float *pA = nullptr, *pB = nullptr;
    cudaGetSymbolAddress((void**)&pA, g_bufA);
    cudaGetSymbolAddress((void**)&pB, g_bufB);

    size_t sm1 = (size_t)(FIN * 64 + FIN * 128) * 4;            // 98304
    size_t smA = (size_t)(HID * 64 + HID * 128 + 128) * 4;      // 49664
    size_t sm4 = (size_t)(HID * 64 + HID * 128) * 4;            // 49152
    cudaFuncSetAttribute(k_gemm<FIN, HID, false, true, true, false>,
                         cudaFuncAttributeMaxDynamicSharedMemorySize, (int)sm1);
    cudaFuncSetAttribute(k_gemm<HID, HID, true, false, false, false>,
                         cudaFuncAttributeMaxDynamicSharedMemorySize, (int)smA);
    cudaFuncSetAttribute(k_gemm<HID, NCLS, false, true, false, true>,
                         cudaFuncAttributeMaxDynamicSharedMemorySize, (int)sm4);

    // side stream + fork/join events, created once on the first (uncaptured)
    // correctness call; reused on the capture call where they become graph edges.
    static cudaStream_t s_side = nullptr;
    static cudaEvent_t  ev_fork = nullptr, ev_join = nullptr;
    if (!s_side) {
        cudaStreamCreateWithFlags(&s_side, cudaStreamNonBlocking);
        cudaEventCreateWithFlags(&ev_fork, cudaEventDisableTiming);
        cudaEventCreateWithFlags(&ev_join, cudaEventDisableTiming);
    }

    const int NTILES = (NNODES + 127) / 128;

    // main: init (zeroing + dtype detect), then fork
    k_init<<<(NNODES + 255) / 256, 256>>>((const int*)ei, in_sizes[1]);
    cudaEventRecord(ev_fork, 0);
    cudaStreamWaitEvent(s_side, ev_fork, 0);

    // side: CSR chain (independent of GEMM1/2)
    k_convert_hist<<<(E + 255) / 256, 256, 0, s_side>>>(ei, E);
    k_scan<<<(NNODES + 1023) / 1024, 1024, 0, s_side>>>();
    k_scatter<<<(E + 255) / 256, 256, 0, s_side>>>(E);
    cudaEventRecord(ev_join, s_side);

    // main: h1 = relu(x @ W1 + b1)
    k_gemm<FIN, HID, false, true, true, false><<<NTILES, 128, sm1>>>(
        x, W1, b1, nullptr, nullptr, pA, -1);
    // main: hc0 = h1 @ Wc0 ; attention dots + max
    k_gemm<HID, HID, true, false, false, false><<<NTILES, 128, smA>>>(
        pA, Wc0, nullptr, as0, ad0, pB, 0);

    // join CSR before aggregation
    cudaStreamWaitEvent(0, ev_join, 0);
    k_agg<<<(NNODES * 32 + 255) / 256, 256>>>(pB, bi0, pA, 1, 0);
    // hc1 = g0 @ Wc1 ; attention dots + max
    k_gemm<HID, HID, true, false, false, false><<<NTILES, 128, smA>>>(
        pA, Wc1, nullptr, as1, ad1, pB, 1);
    k_agg<<<(NNODES * 32 + 255) / 256, 256>>>(pB, bi1, pA, 0, 1);
    // logits + fused log_softmax
    k_gemm<HID, NCLS, false, true, false, true><<<NTILES, 128, sm4>>>(
        pA, W2, b2, nullptr, nullptr, outp, -1);
}